// round 5
// baseline (speedup 1.0000x reference)
#include <cuda_runtime.h>
#include <cuda_bf16.h>
#include <cstdint>

#define N_NODES 32768
#define N_EDGES 524288
#define NH      4
#define HDIM    128
#define HD      512
#define HID_    128
#define DFF_    2048
#define SLOPE_  0.2f
#define EPS_    1e-5f

// ---------------- scratch ----------------------------------------------------
__device__ float    g_ft [N_NODES*HD];
__device__ float    g_res[N_NODES*HD];
__device__ float    g_el [N_NODES*NH];
__device__ float    g_er [N_NODES*NH];
__device__ float    g_sc [N_EDGES*NH];      // exp weights, edge order
__device__ float    g_z  [N_NODES*NH];
__device__ int      g_deg[N_NODES];
__device__ int      g_cursor[N_NODES];
__device__ int      g_rowptr[N_NODES+1];
__device__ int      g_esrc[N_EDGES];        // CSR-sorted src
__device__ float    g_wsH[NH*N_EDGES];      // CSR-sorted weights, head-major
__device__ float    g_x1 [N_NODES*HID_];

// pre-packed MMA B fragments (uint4 per lane: {bh0,bh1,bl0,bl1})
__device__ __align__(16) uint4 g_w1f[32*8*8*32];    // W1^T  (c,kk,nt8,lane)
__device__ __align__(16) uint4 g_w2f[32*4*16*32];   // W2^T  (c,kk,nt16,lane)
__device__ __align__(16) uint4 g_wff[4*8*16*32];    // W_fc^T (y,kk,nt16,lane)
__device__ __align__(16) uint4 g_wrf[4*8*16*32];    // W_res^T
__device__ __align__(16) uint4 g_wmf[4*8*16*32];    // W_mha^T (c,kk,nt16,lane)

// ---------------- helpers ----------------------------------------------------
__device__ __forceinline__ uint32_t smem_u32(const void* p){
    uint32_t a;
    asm("{ .reg .u64 t; cvta.to.shared.u64 t, %1; cvt.u32.u64 %0, t; }" : "=r"(a) : "l"(p));
    return a;
}
__device__ __forceinline__ void ldsm4(unsigned* r, uint32_t addr){
    asm volatile("ldmatrix.sync.aligned.m8n8.x4.shared.b16 {%0,%1,%2,%3}, [%4];"
        : "=r"(r[0]),"=r"(r[1]),"=r"(r[2]),"=r"(r[3]) : "r"(addr));
}
__device__ __forceinline__ void mma_bf16(float* c, const unsigned* a, unsigned b0, unsigned b1){
    asm volatile("mma.sync.aligned.m16n8k16.row.col.f32.bf16.bf16.f32 "
        "{%0,%1,%2,%3},{%4,%5,%6,%7},{%8,%9},{%0,%1,%2,%3};"
        : "+f"(c[0]),"+f"(c[1]),"+f"(c[2]),"+f"(c[3])
        : "r"(a[0]),"r"(a[1]),"r"(a[2]),"r"(a[3]),"r"(b0),"r"(b1));
}
__device__ __forceinline__ void bsplit(float v, __nv_bfloat16& hi, __nv_bfloat16& lo){
    hi = __float2bfloat16(v);
    lo = __float2bfloat16(v - __bfloat162float(hi));
}
__device__ __forceinline__ uint32_t packhi(float a, float b){
    __nv_bfloat162 t; t.x=__float2bfloat16(a); t.y=__float2bfloat16(b);
    return *(uint32_t*)&t;
}
__device__ __forceinline__ uint32_t packlo(float a, float b){
    __nv_bfloat162 t;
    t.x = __float2bfloat16(a - __bfloat162float(__float2bfloat16(a)));
    t.y = __float2bfloat16(b - __bfloat162float(__float2bfloat16(b)));
    return *(uint32_t*)&t;
}
__device__ __forceinline__ uint4 pack4(float v0, float v1, float v2, float v3){
    uint4 r;
    r.x = packhi(v0,v1); r.y = packhi(v2,v3);
    r.z = packlo(v0,v1); r.w = packlo(v2,v3);
    return r;
}

// ---------------- init ---------------------------------------------------------
__global__ void k_init(){
    int i = blockIdx.x*256 + threadIdx.x;
    g_z[i] = 0.f;
    if (i < N_NODES){ g_deg[i] = 0; g_cursor[i] = 0; }
}

// ---------------- prep: weights -> B-fragment-packed hi/lo bf16 ----------------
__global__ void k_prep(const float* __restrict__ W1, const float* __restrict__ W2,
                       const float* __restrict__ Wfc, const float* __restrict__ Wres,
                       const float* __restrict__ Wm){
    int i = blockIdx.x*256 + threadIdx.x;   // 0..65535
    int lane = i & 31;
    int r2 = lane >> 2;          // row-in-8
    int c2 = (lane & 3) * 2;     // k pair base
    {   // W1 [k=128][n=2048]
        int nt=(i>>5)&7, kk=(i>>8)&7, c=i>>11;
        int n = c*64 + nt*8 + r2;
        int k = kk*16 + c2;
        g_w1f[i] = pack4(W1[k*2048+n], W1[(k+1)*2048+n],
                         W1[(k+8)*2048+n], W1[(k+9)*2048+n]);
    }
    {   // W2 [k2=2048][n=128]
        int nt=(i>>5)&15, kk=(i>>9)&3, c=i>>11;
        int n = nt*8 + r2;
        int k2 = c*64 + kk*16 + c2;
        g_w2f[i] = pack4(W2[k2*128+n], W2[(k2+1)*128+n],
                         W2[(k2+8)*128+n], W2[(k2+9)*128+n]);
    }
    if (i < 16384){
        int nt=(i>>5)&15, kk=(i>>9)&7, y=i>>12;
        {   // Wfc/Wres [k=128][n=512]
            int n = y*128 + nt*8 + r2;
            int k = kk*16 + c2;
            g_wff[i] = pack4(Wfc[k*512+n], Wfc[(k+1)*512+n],
                             Wfc[(k+8)*512+n], Wfc[(k+9)*512+n]);
            g_wrf[i] = pack4(Wres[k*512+n], Wres[(k+1)*512+n],
                             Wres[(k+8)*512+n], Wres[(k+9)*512+n]);
        }
        {   // Wm [k2=512][n=128]
            int n = nt*8 + r2;
            int k2 = y*128 + kk*16 + c2;
            g_wmf[i] = pack4(Wm[k2*128+n], Wm[(k2+1)*128+n],
                             Wm[(k2+8)*128+n], Wm[(k2+9)*128+n]);
        }
    }
}

// ---------------- GEMM A via mma, B frags from global -----------------------
#define GA_AH 0
#define GA_AL 34816
#define SMEM_GA 69632

__global__ __launch_bounds__(256,2) void k_gemmA_mma(const float* __restrict__ h){
    extern __shared__ char smem[];
    __nv_bfloat16* ah_s = (__nv_bfloat16*)(smem+GA_AH);
    __nv_bfloat16* al_s = (__nv_bfloat16*)(smem+GA_AL);
    const uint32_t sb = smem_u32(smem);
    const int tid = threadIdx.x, lane = tid&31, w = tid>>5;
    const int m0 = w*16, y = blockIdx.y, col0 = y*128;
    const uint4* __restrict__ BF = blockIdx.z ? g_wrf : g_wff;
    float* __restrict__ C = blockIdx.z ? g_res : g_ft;

    const int a_r = lane & 15, a_c = (lane & 16) >> 1;
    const int q = lane & 3, gq = lane >> 2;

    for (int rt=0; rt<4; rt++){
        const int row0 = (blockIdx.x*4+rt)*128;
        __syncthreads();
        for (int i=tid;i<4096;i+=256){
            int m = i>>5, k4 = (i&31)*4;
            float4 v = *(const float4*)&h[(row0+m)*HID_ + k4];
            __nv_bfloat162 hh, ll;
            bsplit(v.x, hh.x, ll.x); bsplit(v.y, hh.y, ll.y);
            *(__nv_bfloat162*)&ah_s[m*136+k4]   = hh;
            *(__nv_bfloat162*)&al_s[m*136+k4]   = ll;
            bsplit(v.z, hh.x, ll.x); bsplit(v.w, hh.y, ll.y);
            *(__nv_bfloat162*)&ah_s[m*136+k4+2] = hh;
            *(__nv_bfloat162*)&al_s[m*136+k4+2] = ll;
        }
        __syncthreads();

        float acc[16][4];
        #pragma unroll
        for (int i=0;i<16;i++){ acc[i][0]=0.f; acc[i][1]=0.f; acc[i][2]=0.f; acc[i][3]=0.f; }
        #pragma unroll
        for (int kk=0;kk<8;kk++){
            uint32_t aaddr = sb + GA_AH + ((m0+a_r)*136 + kk*16 + a_c)*2;
            unsigned ahf[4], alf[4];
            ldsm4(ahf, aaddr);
            ldsm4(alf, aaddr + (GA_AL-GA_AH));
            #pragma unroll
            for (int nt=0;nt<16;nt++){
                uint4 f = BF[((y*8+kk)*16+nt)*32 + lane];
                mma_bf16(acc[nt], ahf, f.x, f.y);
                mma_bf16(acc[nt], ahf, f.z, f.w);
                mma_bf16(acc[nt], alf, f.x, f.y);
            }
        }
        #pragma unroll
        for (int half=0; half<2; half++){
            int row = row0 + m0 + gq + half*8;
            #pragma unroll
            for (int nt=0;nt<16;nt++){
                int col = col0 + nt*8 + q*2;
                *(float2*)&C[row*HD+col] =
                    make_float2(acc[nt][half*2], acc[nt][half*2+1]);
            }
        }
    }
}

// ---------------- el/er -------------------------------------------------------
__global__ __launch_bounds__(256) void k_eler(const float* __restrict__ attn_l,
                                              const float* __restrict__ attn_r){
    int wid = threadIdx.x>>5, lane = threadIdx.x&31;
    int gw = blockIdx.x*8 + wid;
    int n = gw>>2, hh = gw&3;
    const float4* ft4 = (const float4*)g_ft;
    float4 x  = ft4[n*128 + hh*32 + lane];
    float4 al = ((const float4*)attn_l)[hh*32+lane];
    float4 ar = ((const float4*)attn_r)[hh*32+lane];
    float pl = x.x*al.x + x.y*al.y + x.z*al.z + x.w*al.w;
    float pr = x.x*ar.x + x.y*ar.y + x.z*ar.z + x.w*ar.w;
    #pragma unroll
    for (int off=16; off; off>>=1){
        pl += __shfl_xor_sync(0xffffffffu, pl, off);
        pr += __shfl_xor_sync(0xffffffffu, pr, off);
    }
    if (lane==0){ g_el[n*NH+hh]=pl; g_er[n*NH+hh]=pr; }
}

// ---------------- merged edge pass: w = exp(leaky(sc)), z, deg ----------------
__global__ __launch_bounds__(256) void k_edge(const float* __restrict__ e,
        const int* __restrict__ src, const int* __restrict__ dst,
        const float* __restrict__ W_fe, const float* __restrict__ attn_e){
    __shared__ float ce[NH];
    int wid = threadIdx.x>>5, lane = threadIdx.x&31;
    if (wid < NH){
        float p = 0.f;
        #pragma unroll
        for (int q=0;q<4;q++){
            int d = lane + q*32;
            p += W_fe[wid*HDIM+d]*attn_e[wid*HDIM+d];
        }
        #pragma unroll
        for (int off=16; off; off>>=1) p += __shfl_xor_sync(0xffffffffu, p, off);
        if (lane==0) ce[wid]=p;
    }
    __syncthreads();
    int ei = blockIdx.x*256 + threadIdx.x;
    if (ei >= N_EDGES) return;
    int s = src[ei], d = dst[ei];
    float ev = e[ei];
    float4 els = ((const float4*)g_el)[s];
    float4 erd = ((const float4*)g_er)[d];
    float sc[4];
    sc[0] = els.x + erd.x + ev*ce[0];
    sc[1] = els.y + erd.y + ev*ce[1];
    sc[2] = els.z + erd.z + ev*ce[2];
    sc[3] = els.w + erd.w + ev*ce[3];
    float wv[4];
    #pragma unroll
    for (int hh=0;hh<4;hh++){
        float v = sc[hh];
        v = v > 0.f ? v : SLOPE_*v;
        wv[hh] = expf(v);
        atomicAdd(&g_z[d*NH+hh], wv[hh]);
    }
    *(float4*)&g_sc[ei*4] = make_float4(wv[0],wv[1],wv[2],wv[3]);
    atomicAdd(&g_deg[d], 1);
}

// ---------------- CSR scan -----------------------------------------------------
__global__ __launch_bounds__(1024) void k_scan(){
    __shared__ int sm[1024];
    int t = threadIdx.x;
    int base = t*32;
    int s = 0;
    #pragma unroll
    for (int i=0;i<32;i++) s += g_deg[base+i];
    sm[t]=s; __syncthreads();
    for (int off=1; off<1024; off<<=1){
        int v = (t>=off)? sm[t-off] : 0;
        __syncthreads();
        if (t>=off) sm[t]+=v;
        __syncthreads();
    }
    int run = sm[t]-s;
    for (int i=0;i<32;i++){ g_rowptr[base+i]=run; run += g_deg[base+i]; }
    if (t==1023) g_rowptr[N_NODES]=run;
}

// ---------------- fill: CSR-sorted (src, w) ------------------------------------
__global__ __launch_bounds__(256) void k_fill(const int* __restrict__ src,
                                              const int* __restrict__ dst){
    int ei = blockIdx.x*256 + threadIdx.x;
    if (ei >= N_EDGES) return;
    int d = dst[ei];
    int pos = g_rowptr[d] + atomicAdd(&g_cursor[d], 1);
    g_esrc[pos] = src[ei];
    float4 wv = *(const float4*)&g_sc[ei*4];
    g_wsH[0*N_EDGES+pos] = wv.x;
    g_wsH[1*N_EDGES+pos] = wv.y;
    g_wsH[2*N_EDGES+pos] = wv.z;
    g_wsH[3*N_EDGES+pos] = wv.w;
}

// ---------------- aggregation ---------------------------------------------------
__global__ __launch_bounds__(256) void k_agg(const float* __restrict__ gat_bias){
    int wid = threadIdx.x>>5, lane = threadIdx.x&31;
    int gw = blockIdx.x*8 + wid;
    int n = gw>>2, hh = gw&3;
    int beg = g_rowptr[n], end = g_rowptr[n+1];
    float zz = g_z[n*NH+hh];
    float zi = zz > 0.f ? 1.f/zz : 1.f;
    float4 acc = make_float4(0,0,0,0);
    const float4* ft4 = (const float4*)g_ft;
    const float* wp = g_wsH + hh*N_EDGES;
    int i = beg;
    for (; i+2<=end; i+=2){
        float w0 = wp[i],   w1 = wp[i+1];
        int   s0 = g_esrc[i], s1 = g_esrc[i+1];
        float4 v0 = ft4[s0*128 + hh*32 + lane];
        float4 v1 = ft4[s1*128 + hh*32 + lane];
        acc.x = fmaf(w0, v0.x, fmaf(w1, v1.x, acc.x));
        acc.y = fmaf(w0, v0.y, fmaf(w1, v1.y, acc.y));
        acc.z = fmaf(w0, v0.z, fmaf(w1, v1.z, acc.z));
        acc.w = fmaf(w0, v0.w, fmaf(w1, v1.w, acc.w));
    }
    if (i < end){
        float w0 = wp[i];
        int s0 = g_esrc[i];
        float4 v0 = ft4[s0*128 + hh*32 + lane];
        acc.x = fmaf(w0, v0.x, acc.x);
        acc.y = fmaf(w0, v0.y, acc.y);
        acc.z = fmaf(w0, v0.z, acc.z);
        acc.w = fmaf(w0, v0.w, acc.w);
    }
    int base = n*HD + hh*HDIM + lane*4;
    float4 r  = *(const float4*)&g_res[base];
    float4 bv = *(const float4*)&gat_bias[hh*HDIM + lane*4];
    float4 o;
    o.x = fmaxf(acc.x*zi + r.x + bv.x, 0.f);
    o.y = fmaxf(acc.y*zi + r.y + bv.y, 0.f);
    o.z = fmaxf(acc.z*zi + r.z + bv.z, 0.f);
    o.w = fmaxf(acc.w*zi + r.w + bv.w, 0.f);
    *(float4*)&g_res[base] = o;
}

// ---------------- MHA via mma + relu + residual + LN1 ---------------------------
__global__ __launch_bounds__(256,2) void k_mha_mma(const float* __restrict__ bm,
        const float* __restrict__ h0, const float* __restrict__ g1,
        const float* __restrict__ be1){
    extern __shared__ char smem[];
    __nv_bfloat16* ah_s = (__nv_bfloat16*)(smem+GA_AH);
    __nv_bfloat16* al_s = (__nv_bfloat16*)(smem+GA_AL);
    const uint32_t sb = smem_u32(smem);
    const int tid = threadIdx.x, lane = tid&31, w = tid>>5;
    const int m0 = w*16, row0 = blockIdx.x*128;

    const int a_r = lane & 15, a_c = (lane & 16) >> 1;
    const int q = lane & 3, gq = lane >> 2;

    float acc[16][4];
    #pragma unroll
    for (int i=0;i<16;i++){ acc[i][0]=0.f; acc[i][1]=0.f; acc[i][2]=0.f; acc[i][3]=0.f; }

    for (int c=0; c<4; c++){
        __syncthreads();
        for (int i=tid;i<4096;i+=256){
            int m = i>>5, k4 = (i&31)*4;
            float4 v = *(const float4*)&g_res[(row0+m)*HD + c*128 + k4];
            __nv_bfloat162 hh, ll;
            bsplit(v.x, hh.x, ll.x); bsplit(v.y, hh.y, ll.y);
            *(__nv_bfloat162*)&ah_s[m*136+k4]   = hh;
            *(__nv_bfloat162*)&al_s[m*136+k4]   = ll;
            bsplit(v.z, hh.x, ll.x); bsplit(v.w, hh.y, ll.y);
            *(__nv_bfloat162*)&ah_s[m*136+k4+2] = hh;
            *(__nv_bfloat162*)&al_s[m*136+k4+2] = ll;
        }
        __syncthreads();
        #pragma unroll
        for (int kk=0;kk<8;kk++){
            uint32_t aaddr = sb + GA_AH + ((m0+a_r)*136 + kk*16 + a_c)*2;
            unsigned ahf[4], alf[4];
            ldsm4(ahf, aaddr);
            ldsm4(alf, aaddr + (GA_AL-GA_AH));
            #pragma unroll
            for (int nt=0;nt<16;nt++){
                uint4 f = g_wmf[((c*8+kk)*16+nt)*32 + lane];
                mma_bf16(acc[nt], ahf, f.x, f.y);
                mma_bf16(acc[nt], ahf, f.z, f.w);
                mma_bf16(acc[nt], alf, f.x, f.y);
            }
        }
    }

    #pragma unroll
    for (int half=0; half<2; half++){
        int row = row0 + m0 + gq + half*8;
        float tv[32], s1=0.f, s2=0.f;
        #pragma unroll
        for (int nt=0;nt<16;nt++){
            int col = nt*8 + q*2;
            float t0 = fmaxf(acc[nt][half*2+0] + bm[col],   0.f) + h0[row*HID_+col];
            float t1 = fmaxf(acc[nt][half*2+1] + bm[col+1], 0.f) + h0[row*HID_+col+1];
            tv[nt*2]=t0; tv[nt*2+1]=t1;
            s1 += t0+t1; s2 += t0*t0+t1*t1;
        }
        s1 += __shfl_xor_sync(0xffffffffu, s1, 1); s2 += __shfl_xor_sync(0xffffffffu, s2, 1);
        s1 += __shfl_xor_sync(0xffffffffu, s1, 2); s2 += __shfl_xor_sync(0xffffffffu, s2, 2);
        float mean = s1*(1.f/HID_);
        float var  = s2*(1.f/HID_) - mean*mean;
        float rs   = rsqrtf(var + EPS_);
        #pragma unroll
        for (int nt=0;nt<16;nt++){
            int col = nt*8 + q*2;
            g_x1[row*HID_+col]   = (tv[nt*2]  -mean)*rs*g1[col]   + be1[col];
            g_x1[row*HID_+col+1] = (tv[nt*2+1]-mean)*rs*g1[col+1] + be1[col+1];
        }
    }
}

// ---------------- FFN via mma, B frags from global, 2 CTA/SM -------------------
#define F_XH 0
#define F_XL 34816
#define F_MH 69632
#define F_ML 88064
#define SMEM_FFN 106496

__global__ __launch_bounds__(256,2) void k_ffn_mma(const float* __restrict__ b1v,
        const float* __restrict__ b2v, const float* __restrict__ g2,
        const float* __restrict__ be2, float* __restrict__ out){
    extern __shared__ char smem[];
    __nv_bfloat16* xs_h = (__nv_bfloat16*)(smem+F_XH);
    __nv_bfloat16* xs_l = (__nv_bfloat16*)(smem+F_XL);
    __nv_bfloat16* mid_h= (__nv_bfloat16*)(smem+F_MH);
    __nv_bfloat16* mid_l= (__nv_bfloat16*)(smem+F_ML);
    const uint32_t sb = smem_u32(smem);
    const int tid = threadIdx.x, lane = tid&31, w = tid>>5;
    const int row0 = blockIdx.x*128, m0 = w*16;

    for (int i=tid;i<128*128;i+=256){
        int m=i>>7, k=i&127;
        float v = g_x1[(row0+m)*HID_ + k];
        __nv_bfloat16 hv, lv; bsplit(v, hv, lv);
        xs_h[m*136+k] = hv;
        xs_l[m*136+k] = lv;
    }

    float acc2[16][4];
    #pragma unroll
    for (int i=0;i<16;i++){ acc2[i][0]=0.f; acc2[i][1]=0.f; acc2[i][2]=0.f; acc2[i][3]=0.f; }

    const int a_r = lane & 15, a_c = (lane & 16) >> 1;
    const int q = lane & 3, gq = lane >> 2;

    __syncthreads();

    for (int c=0; c<32; c++){
        float acc1[8][4];
        #pragma unroll
        for (int i=0;i<8;i++){ acc1[i][0]=0.f; acc1[i][1]=0.f; acc1[i][2]=0.f; acc1[i][3]=0.f; }
        #pragma unroll
        for (int kk=0;kk<8;kk++){
            uint32_t aaddr = sb + F_XH + ((m0+a_r)*136 + kk*16 + a_c)*2;
            unsigned ah[4], al[4];
            ldsm4(ah, aaddr);
            ldsm4(al, aaddr + (F_XL - F_XH));
            #pragma unroll
            for (int nt=0;nt<8;nt++){
                uint4 f = g_w1f[((c*8+kk)*8+nt)*32 + lane];
                mma_bf16(acc1[nt], ah, f.x, f.y);
                mma_bf16(acc1[nt], ah, f.z, f.w);
                mma_bf16(acc1[nt], al, f.x, f.y);
            }
        }
        __syncthreads();   // previous GEMM2 done reading mid
        {
            const int r1 = m0 + gq, r2 = r1 + 8;
            #pragma unroll
            for (int nt=0;nt<8;nt++){
                int col = nt*8 + q*2;
                float bb0 = b1v[c*64+col], bb1 = b1v[c*64+col+1];
                float v0 = fmaxf(acc1[nt][0]+bb0, 0.f);
                float v1 = fmaxf(acc1[nt][1]+bb1, 0.f);
                float v2 = fmaxf(acc1[nt][2]+bb0, 0.f);
                float v3 = fmaxf(acc1[nt][3]+bb1, 0.f);
                __nv_bfloat162 hh, ll;
                bsplit(v0, hh.x, ll.x); bsplit(v1, hh.y, ll.y);
                *(__nv_bfloat162*)&mid_h[r1*72+col]=hh;
                *(__nv_bfloat162*)&mid_l[r1*72+col]=ll;
                bsplit(v2, hh.x, ll.x); bsplit(v3, hh.y, ll.y);
                *(__nv_bfloat162*)&mid_h[r2*72+col]=hh;
                *(__nv_bfloat162*)&mid_l[r2*72+col]=ll;
            }
        }
        __syncthreads();

        #pragma unroll
        for (int kk=0;kk<4;kk++){
            uint32_t aaddr = sb + F_MH + ((m0+a_r)*72 + kk*16 + a_c)*2;
            unsigned ah[4], al[4];
            ldsm4(ah, aaddr);
            ldsm4(al, aaddr + (F_ML - F_MH));
            #pragma unroll
            for (int nt=0;nt<16;nt++){
                uint4 f = g_w2f[((c*4+kk)*16+nt)*32 + lane];
                mma_bf16(acc2[nt], ah, f.x, f.y);
                mma_bf16(acc2[nt], ah, f.z, f.w);
                mma_bf16(acc2[nt], al, f.x, f.y);
            }
        }
    }

    #pragma unroll
    for (int half=0; half<2; half++){
        int grow = row0 + m0 + gq + half*8;
        float tv[32], s1=0.f, s2=0.f;
        #pragma unroll
        for (int nt=0;nt<16;nt++){
            int col = nt*8 + q*2;
            float t0 = acc2[nt][half*2+0] + b2v[col]   + g_x1[grow*HID_+col];
            float t1 = acc2[nt][half*2+1] + b2v[col+1] + g_x1[grow*HID_+col+1];
            tv[nt*2]=t0; tv[nt*2+1]=t1;
            s1 += t0+t1; s2 += t0*t0+t1*t1;
        }
        s1 += __shfl_xor_sync(0xffffffffu, s1, 1); s2 += __shfl_xor_sync(0xffffffffu, s2, 1);
        s1 += __shfl_xor_sync(0xffffffffu, s1, 2); s2 += __shfl_xor_sync(0xffffffffu, s2, 2);
        float mean = s1*(1.f/HID_);
        float var  = s2*(1.f/HID_) - mean*mean;
        float rs   = rsqrtf(var + EPS_);
        #pragma unroll
        for (int nt=0;nt<16;nt++){
            int col = nt*8 + q*2;
            out[grow*HID_+col]   = (tv[nt*2]  -mean)*rs*g2[col]   + be2[col];
            out[grow*HID_+col+1] = (tv[nt*2+1]-mean)*rs*g2[col+1] + be2[col+1];
        }
    }
}

// ---------------- launch ---------------------------------------------------------
extern "C" void kernel_launch(void* const* d_in, const int* in_sizes, int n_in,
                              void* d_out, int out_size){
    int o = (in_sizes[4] == 1) ? 1 : 0;
    const float* h       = (const float*)d_in[0];
    const float* e       = (const float*)d_in[1];
    const int*   src     = (const int*)  d_in[2];
    const int*   dst     = (const int*)  d_in[3];
    const float* W_fc    = (const float*)d_in[4+o];
    const float* attn_l  = (const float*)d_in[5+o];
    const float* attn_r  = (const float*)d_in[6+o];
    const float* W_fe    = (const float*)d_in[7+o];
    const float* attn_e  = (const float*)d_in[8+o];
    const float* W_res   = (const float*)d_in[9+o];
    const float* gatb    = (const float*)d_in[10+o];
    const float* W_mha   = (const float*)d_in[11+o];
    const float* b_mha   = (const float*)d_in[12+o];
    const float* n1_g    = (const float*)d_in[13+o];
    const float* n1_b    = (const float*)d_in[14+o];
    const float* n2_g    = (const float*)d_in[15+o];
    const float* n2_b    = (const float*)d_in[16+o];
    const float* W1      = (const float*)d_in[17+o];
    const float* b1      = (const float*)d_in[18+o];
    const float* W2      = (const float*)d_in[19+o];
    const float* b2      = (const float*)d_in[20+o];
    float* out = (float*)d_out;

    cudaFuncSetAttribute(k_ffn_mma,  cudaFuncAttributeMaxDynamicSharedMemorySize, SMEM_FFN);
    cudaFuncSetAttribute(k_gemmA_mma,cudaFuncAttributeMaxDynamicSharedMemorySize, SMEM_GA);
    cudaFuncSetAttribute(k_mha_mma,  cudaFuncAttributeMaxDynamicSharedMemorySize, SMEM_GA);

    k_init<<<512,256>>>();
    k_prep<<<256,256>>>(W1, W2, W_fc, W_res, W_mha);
    dim3 gA(64, 4, 2);
    k_gemmA_mma<<<gA,256,SMEM_GA>>>(h);
    k_eler<<<N_NODES*NH/8,256>>>(attn_l, attn_r);
    k_edge<<<N_EDGES/256,256>>>(e, src, dst, W_fe, attn_e);
    k_scan<<<1,1024>>>();
    k_fill<<<N_EDGES/256,256>>>(src, dst);
    k_agg<<<N_NODES*NH/8,256>>>(gatb);
    k_mha_mma<<<N_NODES/128,256,SMEM_GA>>>(b_mha, h, n1_g, n1_b);
    k_ffn_mma<<<N_NODES/128,256,SMEM_FFN>>>(b1, b2, n2_g, n2_b, out);
}

// round 6
// speedup vs baseline: 1.5121x; 1.5121x over previous
#include <cuda_runtime.h>
#include <cuda_bf16.h>
#include <cstdint>

#define N_NODES 32768
#define N_EDGES 524288
#define NH      4
#define HDIM    128
#define HD      512
#define HID_    128
#define DFF_    2048
#define SLOPE_  0.2f
#define EPS_    1e-5f

// ---------------- scratch ----------------------------------------------------
__device__ float    g_ft [N_NODES*HD];
__device__ float    g_res[N_NODES*HD];
__device__ float    g_el [N_NODES*NH];
__device__ float    g_er [N_NODES*NH];
__device__ float    g_sc [N_EDGES*NH];      // exp weights, edge order
__device__ float    g_z  [N_NODES*NH];
__device__ int      g_deg[N_NODES];
__device__ int      g_cursor[N_NODES];
__device__ int      g_rowptr[N_NODES+1];
__device__ int      g_esrc[N_EDGES];        // CSR-sorted src
__device__ float    g_wsH[NH*N_EDGES];      // CSR-sorted weights, head-major
__device__ float    g_x1 [N_NODES*HID_];

// pre-split hi/lo bf16 transposed weights ([n][k] padded rows)
__device__ __align__(16) __nv_bfloat16 g_w1th[32*64*136];
__device__ __align__(16) __nv_bfloat16 g_w1tl[32*64*136];
__device__ __align__(16) __nv_bfloat16 g_w2th[32*128*72];
__device__ __align__(16) __nv_bfloat16 g_w2tl[32*128*72];
__device__ __align__(16) __nv_bfloat16 g_wfth[512*136];   // W_fc^T
__device__ __align__(16) __nv_bfloat16 g_wftl[512*136];
__device__ __align__(16) __nv_bfloat16 g_wrth[512*136];   // W_res^T
__device__ __align__(16) __nv_bfloat16 g_wrtl[512*136];
__device__ __align__(16) __nv_bfloat16 g_wmth[512*136];   // W_mha^T
__device__ __align__(16) __nv_bfloat16 g_wmtl[512*136];

// ---------------- helpers ------------------------------------------------------
__device__ __forceinline__ uint32_t smem_u32(const void* p){
    uint32_t a;
    asm("{ .reg .u64 t; cvta.to.shared.u64 t, %1; cvt.u32.u64 %0, t; }" : "=r"(a) : "l"(p));
    return a;
}
__device__ __forceinline__ void ldsm4(unsigned* r, uint32_t addr){
    asm volatile("ldmatrix.sync.aligned.m8n8.x4.shared.b16 {%0,%1,%2,%3}, [%4];"
        : "=r"(r[0]),"=r"(r[1]),"=r"(r[2]),"=r"(r[3]) : "r"(addr));
}
__device__ __forceinline__ void ldsm2(unsigned* r, uint32_t addr){
    asm volatile("ldmatrix.sync.aligned.m8n8.x2.shared.b16 {%0,%1}, [%2];"
        : "=r"(r[0]),"=r"(r[1]) : "r"(addr));
}
__device__ __forceinline__ void mma_bf16(float* c, const unsigned* a, const unsigned* b){
    asm volatile("mma.sync.aligned.m16n8k16.row.col.f32.bf16.bf16.f32 "
        "{%0,%1,%2,%3},{%4,%5,%6,%7},{%8,%9},{%0,%1,%2,%3};"
        : "+f"(c[0]),"+f"(c[1]),"+f"(c[2]),"+f"(c[3])
        : "r"(a[0]),"r"(a[1]),"r"(a[2]),"r"(a[3]),"r"(b[0]),"r"(b[1]));
}
__device__ __forceinline__ void bsplit(float v, __nv_bfloat16& hi, __nv_bfloat16& lo){
    hi = __float2bfloat16(v);
    lo = __float2bfloat16(v - __bfloat162float(hi));
}

// ---------------- init ------------------------------------------------------
__global__ void k_init(){
    int i = blockIdx.x*256 + threadIdx.x;
    g_z[i] = 0.f;
    if (i < N_NODES){ g_deg[i] = 0; g_cursor[i] = 0; }
}

// ---------------- prep: weights -> hi/lo bf16 transposed tiles --------------
__global__ void k_prep(const float* __restrict__ W1, const float* __restrict__ W2,
                       const float* __restrict__ Wfc, const float* __restrict__ Wres,
                       const float* __restrict__ Wm){
    int i = blockIdx.x*256 + threadIdx.x;    // 0 .. 262143
    {   // W1 [k=128][n=2048]
        int k = i >> 11, n = i & 2047;
        __nv_bfloat16 hv, lv; bsplit(W1[i], hv, lv);
        int c = n >> 6, nn = n & 63;
        g_w1th[(c*64+nn)*136 + k] = hv;
        g_w1tl[(c*64+nn)*136 + k] = lv;
    }
    {   // W2 [k2=2048][n=128]
        int k2 = i >> 7, n = i & 127;
        __nv_bfloat16 hv, lv; bsplit(W2[i], hv, lv);
        int c = k2 >> 6, kk = k2 & 63;
        g_w2th[(c*128+n)*72 + kk] = hv;
        g_w2tl[(c*128+n)*72 + kk] = lv;
    }
    if (i < 65536){
        {   // Wfc/Wres [k=128][n=512]
            int k = i >> 9, n = i & 511;
            __nv_bfloat16 hv, lv;
            bsplit(Wfc[i], hv, lv);
            g_wfth[n*136 + k] = hv; g_wftl[n*136 + k] = lv;
            bsplit(Wres[i], hv, lv);
            g_wrth[n*136 + k] = hv; g_wrtl[n*136 + k] = lv;
        }
        {   // Wm [k2=512][n=128] -> chunk-major [c][n][136]
            int k2 = i >> 7, n = i & 127;
            __nv_bfloat16 hv, lv; bsplit(Wm[i], hv, lv);
            int c = k2 >> 7, kk = k2 & 127;
            g_wmth[(c*128+n)*136 + kk] = hv;
            g_wmtl[(c*128+n)*136 + kk] = lv;
        }
    }
}

// ---------------- GEMM A via mma: {g_ft,g_res}[N,512] = h @ W ---------------
#define GA_AH 0
#define GA_AL 34816
#define GA_BH 69632
#define GA_BL 104448
#define SMEM_GA 139264

__global__ __launch_bounds__(256,1) void k_gemmA_mma(const float* __restrict__ h){
    extern __shared__ char smem[];
    __nv_bfloat16* ah_s = (__nv_bfloat16*)(smem+GA_AH);
    __nv_bfloat16* al_s = (__nv_bfloat16*)(smem+GA_AL);
    const uint32_t sb = smem_u32(smem);
    const int tid = threadIdx.x, lane = tid&31, w = tid>>5;
    const int m0 = w*16, col0 = blockIdx.y*128;
    const __nv_bfloat16* Bh = blockIdx.z ? g_wrth : g_wfth;
    const __nv_bfloat16* Bl = blockIdx.z ? g_wrtl : g_wftl;
    float* __restrict__ C = blockIdx.z ? g_res : g_ft;

    {   // load B tile
        const uint4* sh = (const uint4*)(Bh + col0*136);
        const uint4* sl = (const uint4*)(Bl + col0*136);
        uint4* th = (uint4*)(smem+GA_BH);
        uint4* tl = (uint4*)(smem+GA_BL);
        #pragma unroll
        for (int q=0;q<9;q++){
            int i = tid + q*256;
            if (i < 2176){ th[i]=sh[i]; tl[i]=sl[i]; }
        }
    }

    const int a_r = lane & 15, a_c = (lane & 16) >> 1;
    const int b_r = lane & 7,  b_c = lane & 8;
    const int q = lane & 3, gq = lane >> 2;

    for (int rt=0; rt<4; rt++){
        const int row0 = (blockIdx.x*4+rt)*128;
        __syncthreads();
        for (int i=tid;i<4096;i+=256){
            int m = i>>5, k4 = (i&31)*4;
            float4 v = *(const float4*)&h[(row0+m)*HID_ + k4];
            __nv_bfloat162 hh, ll;
            bsplit(v.x, hh.x, ll.x); bsplit(v.y, hh.y, ll.y);
            *(__nv_bfloat162*)&ah_s[m*136+k4]   = hh;
            *(__nv_bfloat162*)&al_s[m*136+k4]   = ll;
            bsplit(v.z, hh.x, ll.x); bsplit(v.w, hh.y, ll.y);
            *(__nv_bfloat162*)&ah_s[m*136+k4+2] = hh;
            *(__nv_bfloat162*)&al_s[m*136+k4+2] = ll;
        }
        __syncthreads();

        float acc[16][4];
        #pragma unroll
        for (int i=0;i<16;i++){ acc[i][0]=0.f; acc[i][1]=0.f; acc[i][2]=0.f; acc[i][3]=0.f; }
        #pragma unroll
        for (int kk=0;kk<8;kk++){
            const int k0 = kk*16;
            uint32_t aaddr = sb + GA_AH + ((m0+a_r)*136 + k0 + a_c)*2;
            unsigned ahf[4], alf[4];
            ldsm4(ahf, aaddr);
            ldsm4(alf, aaddr + (GA_AL-GA_AH));
            #pragma unroll
            for (int nt=0;nt<16;nt++){
                uint32_t baddr = sb + GA_BH + ((nt*8+b_r)*136 + k0 + b_c)*2;
                unsigned bh[2], bl[2];
                ldsm2(bh, baddr);
                ldsm2(bl, baddr + (GA_BL-GA_BH));
                mma_bf16(acc[nt], ahf, bh);
                mma_bf16(acc[nt], ahf, bl);
                mma_bf16(acc[nt], alf, bh);
            }
        }
        #pragma unroll
        for (int half=0; half<2; half++){
            int row = row0 + m0 + gq + half*8;
            #pragma unroll
            for (int nt=0;nt<16;nt++){
                int col = col0 + nt*8 + q*2;
                *(float2*)&C[row*HD+col] =
                    make_float2(acc[nt][half*2], acc[nt][half*2+1]);
            }
        }
    }
}

// ---------------- el/er ------------------------------------------------------
__global__ __launch_bounds__(256) void k_eler(const float* __restrict__ attn_l,
                                              const float* __restrict__ attn_r){
    int wid = threadIdx.x>>5, lane = threadIdx.x&31;
    int gw = blockIdx.x*8 + wid;
    int n = gw>>2, hh = gw&3;
    const float4* ft4 = (const float4*)g_ft;
    float4 x  = ft4[n*128 + hh*32 + lane];
    float4 al = ((const float4*)attn_l)[hh*32+lane];
    float4 ar = ((const float4*)attn_r)[hh*32+lane];
    float pl = x.x*al.x + x.y*al.y + x.z*al.z + x.w*al.w;
    float pr = x.x*ar.x + x.y*ar.y + x.z*ar.z + x.w*ar.w;
    #pragma unroll
    for (int off=16; off; off>>=1){
        pl += __shfl_xor_sync(0xffffffffu, pl, off);
        pr += __shfl_xor_sync(0xffffffffu, pr, off);
    }
    if (lane==0){ g_el[n*NH+hh]=pl; g_er[n*NH+hh]=pr; }
}

// ---------------- merged edge pass: w = exp(leaky(sc)), z, deg ----------------
__global__ __launch_bounds__(256) void k_edge(const float* __restrict__ e,
        const int* __restrict__ src, const int* __restrict__ dst,
        const float* __restrict__ W_fe, const float* __restrict__ attn_e){
    __shared__ float ce[NH];
    int wid = threadIdx.x>>5, lane = threadIdx.x&31;
    if (wid < NH){
        float p = 0.f;
        #pragma unroll
        for (int q=0;q<4;q++){
            int d = lane + q*32;
            p += W_fe[wid*HDIM+d]*attn_e[wid*HDIM+d];
        }
        #pragma unroll
        for (int off=16; off; off>>=1) p += __shfl_xor_sync(0xffffffffu, p, off);
        if (lane==0) ce[wid]=p;
    }
    __syncthreads();
    int ei = blockIdx.x*256 + threadIdx.x;
    if (ei >= N_EDGES) return;
    int s = src[ei], d = dst[ei];
    float ev = e[ei];
    float4 els = ((const float4*)g_el)[s];
    float4 erd = ((const float4*)g_er)[d];
    float sc[4];
    sc[0] = els.x + erd.x + ev*ce[0];
    sc[1] = els.y + erd.y + ev*ce[1];
    sc[2] = els.z + erd.z + ev*ce[2];
    sc[3] = els.w + erd.w + ev*ce[3];
    float wv[4];
    #pragma unroll
    for (int hh=0;hh<4;hh++){
        float v = sc[hh];
        v = v > 0.f ? v : SLOPE_*v;
        wv[hh] = expf(v);
        atomicAdd(&g_z[d*NH+hh], wv[hh]);
    }
    *(float4*)&g_sc[ei*4] = make_float4(wv[0],wv[1],wv[2],wv[3]);
    atomicAdd(&g_deg[d], 1);
}

// ---------------- CSR scan ----------------------------------------------------
__global__ __launch_bounds__(1024) void k_scan(){
    __shared__ int sm[1024];
    int t = threadIdx.x;
    int base = t*32;
    int s = 0;
    #pragma unroll
    for (int i=0;i<32;i++) s += g_deg[base+i];
    sm[t]=s; __syncthreads();
    for (int off=1; off<1024; off<<=1){
        int v = (t>=off)? sm[t-off] : 0;
        __syncthreads();
        if (t>=off) sm[t]+=v;
        __syncthreads();
    }
    int run = sm[t]-s;
    for (int i=0;i<32;i++){ g_rowptr[base+i]=run; run += g_deg[base+i]; }
    if (t==1023) g_rowptr[N_NODES]=run;
}

// ---------------- fill: CSR-sorted (src, w) ------------------------------------
__global__ __launch_bounds__(256) void k_fill(const int* __restrict__ src,
                                              const int* __restrict__ dst){
    int ei = blockIdx.x*256 + threadIdx.x;
    if (ei >= N_EDGES) return;
    int d = dst[ei];
    int pos = g_rowptr[d] + atomicAdd(&g_cursor[d], 1);
    g_esrc[pos] = src[ei];
    float4 wv = *(const float4*)&g_sc[ei*4];
    g_wsH[0*N_EDGES+pos] = wv.x;
    g_wsH[1*N_EDGES+pos] = wv.y;
    g_wsH[2*N_EDGES+pos] = wv.z;
    g_wsH[3*N_EDGES+pos] = wv.w;
}

// ---------------- aggregation ---------------------------------------------------
__global__ __launch_bounds__(256) void k_agg(const float* __restrict__ gat_bias){
    int wid = threadIdx.x>>5, lane = threadIdx.x&31;
    int gw = blockIdx.x*8 + wid;
    int n = gw>>2, hh = gw&3;
    int beg = g_rowptr[n], end = g_rowptr[n+1];
    float zz = g_z[n*NH+hh];
    float zi = zz > 0.f ? 1.f/zz : 1.f;
    float4 acc = make_float4(0,0,0,0);
    const float4* ft4 = (const float4*)g_ft;
    const float* wp = g_wsH + hh*N_EDGES;
    int i = beg;
    for (; i+2<=end; i+=2){
        float w0 = wp[i],     w1 = wp[i+1];
        int   s0 = g_esrc[i], s1 = g_esrc[i+1];
        float4 v0 = ft4[s0*128 + hh*32 + lane];
        float4 v1 = ft4[s1*128 + hh*32 + lane];
        acc.x = fmaf(w0, v0.x, fmaf(w1, v1.x, acc.x));
        acc.y = fmaf(w0, v0.y, fmaf(w1, v1.y, acc.y));
        acc.z = fmaf(w0, v0.z, fmaf(w1, v1.z, acc.z));
        acc.w = fmaf(w0, v0.w, fmaf(w1, v1.w, acc.w));
    }
    if (i < end){
        float w0 = wp[i];
        int s0 = g_esrc[i];
        float4 v0 = ft4[s0*128 + hh*32 + lane];
        acc.x = fmaf(w0, v0.x, acc.x);
        acc.y = fmaf(w0, v0.y, acc.y);
        acc.z = fmaf(w0, v0.z, acc.z);
        acc.w = fmaf(w0, v0.w, acc.w);
    }
    int base = n*HD + hh*HDIM + lane*4;
    float4 r  = *(const float4*)&g_res[base];
    float4 bv = *(const float4*)&gat_bias[hh*HDIM + lane*4];
    float4 o;
    o.x = fmaxf(acc.x*zi + r.x + bv.x, 0.f);
    o.y = fmaxf(acc.y*zi + r.y + bv.y, 0.f);
    o.z = fmaxf(acc.z*zi + r.z + bv.z, 0.f);
    o.w = fmaxf(acc.w*zi + r.w + bv.w, 0.f);
    *(float4*)&g_res[base] = o;
}

// ---------------- MHA via mma + relu + residual + LN1 -----------------------
__global__ __launch_bounds__(256,1) void k_mha_mma(const float* __restrict__ bm,
        const float* __restrict__ h0, const float* __restrict__ g1,
        const float* __restrict__ be1){
    extern __shared__ char smem[];
    __nv_bfloat16* ah_s = (__nv_bfloat16*)(smem+GA_AH);
    __nv_bfloat16* al_s = (__nv_bfloat16*)(smem+GA_AL);
    const uint32_t sb = smem_u32(smem);
    const int tid = threadIdx.x, lane = tid&31, w = tid>>5;
    const int m0 = w*16, row0 = blockIdx.x*128;

    const int a_r = lane & 15, a_c = (lane & 16) >> 1;
    const int b_r = lane & 7,  b_c = lane & 8;
    const int q = lane & 3, gq = lane >> 2;

    float acc[16][4];
    #pragma unroll
    for (int i=0;i<16;i++){ acc[i][0]=0.f; acc[i][1]=0.f; acc[i][2]=0.f; acc[i][3]=0.f; }

    for (int c=0; c<4; c++){
        __syncthreads();
        for (int i=tid;i<4096;i+=256){
            int m = i>>5, k4 = (i&31)*4;
            float4 v = *(const float4*)&g_res[(row0+m)*HD + c*128 + k4];
            __nv_bfloat162 hh, ll;
            bsplit(v.x, hh.x, ll.x); bsplit(v.y, hh.y, ll.y);
            *(__nv_bfloat162*)&ah_s[m*136+k4]   = hh;
            *(__nv_bfloat162*)&al_s[m*136+k4]   = ll;
            bsplit(v.z, hh.x, ll.x); bsplit(v.w, hh.y, ll.y);
            *(__nv_bfloat162*)&ah_s[m*136+k4+2] = hh;
            *(__nv_bfloat162*)&al_s[m*136+k4+2] = ll;
        }
        {
            const uint4* sh = (const uint4*)(g_wmth + c*128*136);
            const uint4* sl = (const uint4*)(g_wmtl + c*128*136);
            uint4* th = (uint4*)(smem+GA_BH);
            uint4* tl = (uint4*)(smem+GA_BL);
            #pragma unroll
            for (int qq=0;qq<9;qq++){
                int i = tid + qq*256;
                if (i < 2176){ th[i]=sh[i]; tl[i]=sl[i]; }
            }
        }
        __syncthreads();
        #pragma unroll
        for (int kk=0;kk<8;kk++){
            const int k0 = kk*16;
            uint32_t aaddr = sb + GA_AH + ((m0+a_r)*136 + k0 + a_c)*2;
            unsigned ahf[4], alf[4];
            ldsm4(ahf, aaddr);
            ldsm4(alf, aaddr + (GA_AL-GA_AH));
            #pragma unroll
            for (int nt=0;nt<16;nt++){
                uint32_t baddr = sb + GA_BH + ((nt*8+b_r)*136 + k0 + b_c)*2;
                unsigned bh[2], bl[2];
                ldsm2(bh, baddr);
                ldsm2(bl, baddr + (GA_BL-GA_BH));
                mma_bf16(acc[nt], ahf, bh);
                mma_bf16(acc[nt], ahf, bl);
                mma_bf16(acc[nt], alf, bh);
            }
        }
    }

    #pragma unroll
    for (int half=0; half<2; half++){
        int row = row0 + m0 + gq + half*8;
        float tv[32], s1=0.f, s2=0.f;
        #pragma unroll
        for (int nt=0;nt<16;nt++){
            int col = nt*8 + q*2;
            float t0 = fmaxf(acc[nt][half*2+0] + bm[col],   0.f) + h0[row*HID_+col];
            float t1 = fmaxf(acc[nt][half*2+1] + bm[col+1], 0.f) + h0[row*HID_+col+1];
            tv[nt*2]=t0; tv[nt*2+1]=t1;
            s1 += t0+t1; s2 += t0*t0+t1*t1;
        }
        s1 += __shfl_xor_sync(0xffffffffu, s1, 1); s2 += __shfl_xor_sync(0xffffffffu, s2, 1);
        s1 += __shfl_xor_sync(0xffffffffu, s1, 2); s2 += __shfl_xor_sync(0xffffffffu, s2, 2);
        float mean = s1*(1.f/HID_);
        float var  = s2*(1.f/HID_) - mean*mean;
        float rs   = rsqrtf(var + EPS_);
        #pragma unroll
        for (int nt=0;nt<16;nt++){
            int col = nt*8 + q*2;
            g_x1[row*HID_+col]   = (tv[nt*2]  -mean)*rs*g1[col]   + be1[col];
            g_x1[row*HID_+col+1] = (tv[nt*2+1]-mean)*rs*g1[col+1] + be1[col+1];
        }
    }
}

// ---------------- FFN via mma.sync (bf16 hi/lo split) + residual + LN2 ------
#define SM_XS_H 0
#define SM_XS_L 34816
#define SM_W1H  69632
#define SM_W1L  87040
#define SM_W2H  104448
#define SM_W2L  122880
#define SM_MIDH 141312
#define SM_MIDL 159744
#define SMEM_FFN 178176

__global__ __launch_bounds__(256,1) void k_ffn_mma(const float* __restrict__ b1v,
        const float* __restrict__ b2v, const float* __restrict__ g2,
        const float* __restrict__ be2, float* __restrict__ out){
    extern __shared__ char smem[];
    __nv_bfloat16* xs_h = (__nv_bfloat16*)(smem+SM_XS_H);
    __nv_bfloat16* xs_l = (__nv_bfloat16*)(smem+SM_XS_L);
    __nv_bfloat16* mid_h= (__nv_bfloat16*)(smem+SM_MIDH);
    __nv_bfloat16* mid_l= (__nv_bfloat16*)(smem+SM_MIDL);
    const uint32_t sb = smem_u32(smem);
    const int tid = threadIdx.x, lane = tid&31, w = tid>>5;
    const int row0 = blockIdx.x*128, m0 = w*16;

    for (int i=tid;i<128*128;i+=256){
        int m=i>>7, k=i&127;
        float v = g_x1[(row0+m)*HID_ + k];
        __nv_bfloat16 hv, lv; bsplit(v, hv, lv);
        xs_h[m*136+k] = hv;
        xs_l[m*136+k] = lv;
    }

    float acc2[16][4];
    #pragma unroll
    for (int i=0;i<16;i++){ acc2[i][0]=0.f; acc2[i][1]=0.f; acc2[i][2]=0.f; acc2[i][3]=0.f; }

    const int a_r = lane & 15;
    const int a_c = (lane & 16) >> 1;
    const int b_r = lane & 7;
    const int b_c = lane & 8;
    const int q = lane & 3, gq = lane >> 2;

    for (int c=0; c<32; c++){
        __syncthreads();
        {
            const uint4* s1h = (const uint4*)(g_w1th + c*64*136);
            const uint4* s1l = (const uint4*)(g_w1tl + c*64*136);
            const uint4* s2h = (const uint4*)(g_w2th + c*128*72);
            const uint4* s2l = (const uint4*)(g_w2tl + c*128*72);
            uint4* t1h = (uint4*)(smem+SM_W1H); uint4* t1l = (uint4*)(smem+SM_W1L);
            uint4* t2h = (uint4*)(smem+SM_W2H); uint4* t2l = (uint4*)(smem+SM_W2L);
            for (int i=tid;i<1088;i+=256){ t1h[i]=s1h[i]; t1l[i]=s1l[i]; }
            for (int i=tid;i<1152;i+=256){ t2h[i]=s2h[i]; t2l[i]=s2l[i]; }
        }
        __syncthreads();

        float acc1[8][4];
        #pragma unroll
        for (int i=0;i<8;i++){ acc1[i][0]=0.f; acc1[i][1]=0.f; acc1[i][2]=0.f; acc1[i][3]=0.f; }
        #pragma unroll
        for (int kk=0;kk<8;kk++){
            const int k0 = kk*16;
            uint32_t aaddr = sb + SM_XS_H + ((m0+a_r)*136 + k0 + a_c)*2;
            unsigned ah[4], al[4];
            ldsm4(ah, aaddr);
            ldsm4(al, aaddr + (SM_XS_L - SM_XS_H));
            unsigned bh[8][2], bl[8][2];
            #pragma unroll
            for (int nt=0;nt<8;nt++){
                uint32_t baddr = sb + SM_W1H + ((nt*8+b_r)*136 + k0 + b_c)*2;
                ldsm2(bh[nt], baddr);
                ldsm2(bl[nt], baddr + (SM_W1L - SM_W1H));
            }
            #pragma unroll
            for (int nt=0;nt<8;nt++){
                mma_bf16(acc1[nt], ah, bh[nt]);
                mma_bf16(acc1[nt], ah, bl[nt]);
                mma_bf16(acc1[nt], al, bh[nt]);
            }
        }
        {
            const int r1 = m0 + gq, r2 = r1 + 8;
            #pragma unroll
            for (int nt=0;nt<8;nt++){
                int col = nt*8 + q*2;
                float bb0 = b1v[c*64+col], bb1 = b1v[c*64+col+1];
                float v0 = fmaxf(acc1[nt][0]+bb0, 0.f);
                float v1 = fmaxf(acc1[nt][1]+bb1, 0.f);
                float v2 = fmaxf(acc1[nt][2]+bb0, 0.f);
                float v3 = fmaxf(acc1[nt][3]+bb1, 0.f);
                __nv_bfloat162 hh, ll;
                bsplit(v0, hh.x, ll.x); bsplit(v1, hh.y, ll.y);
                *(__nv_bfloat162*)&mid_h[r1*72+col]=hh;
                *(__nv_bfloat162*)&mid_l[r1*72+col]=ll;
                bsplit(v2, hh.x, ll.x); bsplit(v3, hh.y, ll.y);
                *(__nv_bfloat162*)&mid_h[r2*72+col]=hh;
                *(__nv_bfloat162*)&mid_l[r2*72+col]=ll;
            }
        }
        __syncthreads();

        #pragma unroll
        for (int kk=0;kk<4;kk++){
            const int k0 = kk*16;
            uint32_t aaddr = sb + SM_MIDH + ((m0+a_r)*72 + k0 + a_c)*2;
            unsigned ah[4], al[4];
            ldsm4(ah, aaddr);
            ldsm4(al, aaddr + (SM_MIDL - SM_MIDH));
            #pragma unroll
            for (int nt=0;nt<16;nt++){
                uint32_t baddr = sb + SM_W2H + ((nt*8+b_r)*72 + k0 + b_c)*2;
                unsigned bh[2], bl[2];
                ldsm2(bh, baddr);
                ldsm2(bl, baddr + (SM_W2L - SM_W2H));
                mma_bf16(acc2[nt], ah, bh);
                mma_bf16(acc2[nt], ah, bl);
                mma_bf16(acc2[nt], al, bh);
            }
        }
    }

    #pragma unroll
    for (int half=0; half<2; half++){
        int grow = row0 + m0 + gq + half*8;
        float tv[32], s1=0.f, s2=0.f;
        #pragma unroll
        for (int nt=0;nt<16;nt++){
            int col = nt*8 + q*2;
            float t0 = acc2[nt][half*2+0] + b2v[col]   + g_x1[grow*HID_+col];
            float t1 = acc2[nt][half*2+1] + b2v[col+1] + g_x1[grow*HID_+col+1];
            tv[nt*2]=t0; tv[nt*2+1]=t1;
            s1 += t0+t1; s2 += t0*t0+t1*t1;
        }
        s1 += __shfl_xor_sync(0xffffffffu, s1, 1); s2 += __shfl_xor_sync(0xffffffffu, s2, 1);
        s1 += __shfl_xor_sync(0xffffffffu, s1, 2); s2 += __shfl_xor_sync(0xffffffffu, s2, 2);
        float mean = s1*(1.f/HID_);
        float var  = s2*(1.f/HID_) - mean*mean;
        float rs   = rsqrtf(var + EPS_);
        #pragma unroll
        for (int nt=0;nt<16;nt++){
            int col = nt*8 + q*2;
            out[grow*HID_+col]   = (tv[nt*2]  -mean)*rs*g2[col]   + be2[col];
            out[grow*HID_+col+1] = (tv[nt*2+1]-mean)*rs*g2[col+1] + be2[col+1];
        }
    }
}

// ---------------- launch ----------------------------------------------------
extern "C" void kernel_launch(void* const* d_in, const int* in_sizes, int n_in,
                              void* d_out, int out_size){
    int o = (in_sizes[4] == 1) ? 1 : 0;
    const float* h       = (const float*)d_in[0];
    const float* e       = (const float*)d_in[1];
    const int*   src     = (const int*)  d_in[2];
    const int*   dst     = (const int*)  d_in[3];
    const float* W_fc    = (const float*)d_in[4+o];
    const float* attn_l  = (const float*)d_in[5+o];
    const float* attn_r  = (const float*)d_in[6+o];
    const float* W_fe    = (const float*)d_in[7+o];
    const float* attn_e  = (const float*)d_in[8+o];
    const float* W_res   = (const float*)d_in[9+o];
    const float* gatb    = (const float*)d_in[10+o];
    const float* W_mha   = (const float*)d_in[11+o];
    const float* b_mha   = (const float*)d_in[12+o];
    const float* n1_g    = (const float*)d_in[13+o];
    const float* n1_b    = (const float*)d_in[14+o];
    const float* n2_g    = (const float*)d_in[15+o];
    const float* n2_b    = (const float*)d_in[16+o];
    const float* W1      = (const float*)d_in[17+o];
    const float* b1      = (const float*)d_in[18+o];
    const float* W2      = (const float*)d_in[19+o];
    const float* b2      = (const float*)d_in[20+o];
    float* out = (float*)d_out;

    cudaFuncSetAttribute(k_ffn_mma,  cudaFuncAttributeMaxDynamicSharedMemorySize, SMEM_FFN);
    cudaFuncSetAttribute(k_gemmA_mma,cudaFuncAttributeMaxDynamicSharedMemorySize, SMEM_GA);
    cudaFuncSetAttribute(k_mha_mma,  cudaFuncAttributeMaxDynamicSharedMemorySize, SMEM_GA);

    k_init<<<512,256>>>();
    k_prep<<<1024,256>>>(W1, W2, W_fc, W_res, W_mha);
    dim3 gA(64, 4, 2);
    k_gemmA_mma<<<gA,256,SMEM_GA>>>(h);
    k_eler<<<N_NODES*NH/8,256>>>(attn_l, attn_r);
    k_edge<<<N_EDGES/256,256>>>(e, src, dst, W_fe, attn_e);
    k_scan<<<1,1024>>>();
    k_fill<<<N_EDGES/256,256>>>(src, dst);
    k_agg<<<N_NODES*NH/8,256>>>(gatb);
    k_mha_mma<<<N_NODES/128,256,SMEM_GA>>>(b_mha, h, n1_g, n1_b);
    k_ffn_mma<<<N_NODES/128,256,SMEM_FFN>>>(b1, b2, n2_g, n2_b, out);
}

// round 7
// speedup vs baseline: 1.5235x; 1.0075x over previous
#include <cuda_runtime.h>
#include <cuda_bf16.h>
#include <cstdint>

#define N_NODES 32768
#define N_EDGES 524288
#define NH      4
#define HDIM    128
#define HD      512
#define HID_    128
#define DFF_    2048
#define SLOPE_  0.2f
#define EPS_    1e-5f

// ---------------- scratch ----------------------------------------------------
__device__ float    g_ft [N_NODES*HD];
__device__ float    g_res[N_NODES*HD];
__device__ float    g_el [N_NODES*NH];
__device__ float    g_er [N_NODES*NH];
__device__ float    g_z  [N_NODES*NH];
__device__ int      g_deg[N_NODES];
__device__ int      g_cursor[N_NODES];
__device__ int      g_rowptr[N_NODES+1];
__device__ int      g_esrc[N_EDGES];        // CSR-sorted src
__device__ float    g_wsH[NH*N_EDGES];      // CSR-sorted weights, head-major
__device__ float    g_x1 [N_NODES*HID_];

// pre-split hi/lo bf16 transposed weights ([n][k] padded rows)
__device__ __align__(16) __nv_bfloat16 g_w1th[32*64*136];
__device__ __align__(16) __nv_bfloat16 g_w1tl[32*64*136];
__device__ __align__(16) __nv_bfloat16 g_w2th[32*128*72];
__device__ __align__(16) __nv_bfloat16 g_w2tl[32*128*72];
__device__ __align__(16) __nv_bfloat16 g_wfth[512*136];   // W_fc^T
__device__ __align__(16) __nv_bfloat16 g_wftl[512*136];
__device__ __align__(16) __nv_bfloat16 g_wrth[512*136];   // W_res^T
__device__ __align__(16) __nv_bfloat16 g_wrtl[512*136];
__device__ __align__(16) __nv_bfloat16 g_wmth[512*136];   // W_mha^T
__device__ __align__(16) __nv_bfloat16 g_wmtl[512*136];

// ---------------- helpers ------------------------------------------------------
__device__ __forceinline__ uint32_t smem_u32(const void* p){
    uint32_t a;
    asm("{ .reg .u64 t; cvta.to.shared.u64 t, %1; cvt.u32.u64 %0, t; }" : "=r"(a) : "l"(p));
    return a;
}
__device__ __forceinline__ void ldsm4(unsigned* r, uint32_t addr){
    asm volatile("ldmatrix.sync.aligned.m8n8.x4.shared.b16 {%0,%1,%2,%3}, [%4];"
        : "=r"(r[0]),"=r"(r[1]),"=r"(r[2]),"=r"(r[3]) : "r"(addr));
}
__device__ __forceinline__ void mma_bf16(float* c, const unsigned* a, unsigned b0, unsigned b1){
    asm volatile("mma.sync.aligned.m16n8k16.row.col.f32.bf16.bf16.f32 "
        "{%0,%1,%2,%3},{%4,%5,%6,%7},{%8,%9},{%0,%1,%2,%3};"
        : "+f"(c[0]),"+f"(c[1]),"+f"(c[2]),"+f"(c[3])
        : "r"(a[0]),"r"(a[1]),"r"(a[2]),"r"(a[3]),"r"(b0),"r"(b1));
}
__device__ __forceinline__ void bsplit(float v, __nv_bfloat16& hi, __nv_bfloat16& lo){
    hi = __float2bfloat16(v);
    lo = __float2bfloat16(v - __bfloat162float(hi));
}

// ---------------- init ------------------------------------------------------
__global__ void k_init(){
    int i = blockIdx.x*256 + threadIdx.x;
    g_z[i] = 0.f;
    if (i < N_NODES){ g_deg[i] = 0; g_cursor[i] = 0; }
}

// ---------------- prep: weights -> hi/lo bf16 transposed tiles --------------
__global__ void k_prep(const float* __restrict__ W1, const float* __restrict__ W2,
                       const float* __restrict__ Wfc, const float* __restrict__ Wres,
                       const float* __restrict__ Wm){
    int i = blockIdx.x*256 + threadIdx.x;    // 0 .. 262143
    {   // W1 [k=128][n=2048]
        int k = i >> 11, n = i & 2047;
        __nv_bfloat16 hv, lv; bsplit(W1[i], hv, lv);
        int c = n >> 6, nn = n & 63;
        g_w1th[(c*64+nn)*136 + k] = hv;
        g_w1tl[(c*64+nn)*136 + k] = lv;
    }
    {   // W2 [k2=2048][n=128]
        int k2 = i >> 7, n = i & 127;
        __nv_bfloat16 hv, lv; bsplit(W2[i], hv, lv);
        int c = k2 >> 6, kk = k2 & 63;
        g_w2th[(c*128+n)*72 + kk] = hv;
        g_w2tl[(c*128+n)*72 + kk] = lv;
    }
    if (i < 65536){
        {   // Wfc/Wres [k=128][n=512]
            int k = i >> 9, n = i & 511;
            __nv_bfloat16 hv, lv;
            bsplit(Wfc[i], hv, lv);
            g_wfth[n*136 + k] = hv; g_wftl[n*136 + k] = lv;
            bsplit(Wres[i], hv, lv);
            g_wrth[n*136 + k] = hv; g_wrtl[n*136 + k] = lv;
        }
        {   // Wm [k2=512][n=128] -> chunk-major [c][n][136]
            int k2 = i >> 7, n = i & 127;
            __nv_bfloat16 hv, lv; bsplit(Wm[i], hv, lv);
            int c = k2 >> 7, kk = k2 & 127;
            g_wmth[(c*128+n)*136 + kk] = hv;
            g_wmtl[(c*128+n)*136 + kk] = lv;
        }
    }
}

// ---------------- degree count ------------------------------------------------
__global__ __launch_bounds__(256) void k_deg(const int* __restrict__ dst){
    int ei = blockIdx.x*256 + threadIdx.x;
    if (ei < N_EDGES) atomicAdd(&g_deg[dst[ei]], 1);
}

// ---------------- GEMM A via mma (+fused el/er on z==0) ---------------------
#define GA_AH 0
#define GA_AL 34816
#define GA_BH 69632
#define GA_BL 104448
#define SMEM_GA 139264

__global__ __launch_bounds__(256,1) void k_gemmA_mma(const float* __restrict__ h,
        const float* __restrict__ attn_l, const float* __restrict__ attn_r){
    extern __shared__ char smem[];
    __shared__ float s_al[128], s_ar[128];
    __nv_bfloat16* ah_s = (__nv_bfloat16*)(smem+GA_AH);
    __nv_bfloat16* al_s = (__nv_bfloat16*)(smem+GA_AL);
    const uint32_t sb = smem_u32(smem);
    const int tid = threadIdx.x, lane = tid&31, w = tid>>5;
    const int m0 = w*16, col0 = blockIdx.y*128;
    const __nv_bfloat16* Bh = blockIdx.z ? g_wrth : g_wfth;
    const __nv_bfloat16* Bl = blockIdx.z ? g_wrtl : g_wftl;
    float* __restrict__ C = blockIdx.z ? g_res : g_ft;

    if (blockIdx.z==0 && tid<128){
        s_al[tid] = attn_l[col0+tid];
        s_ar[tid] = attn_r[col0+tid];
    }
    {   // load B tile
        const uint4* sh = (const uint4*)(Bh + col0*136);
        const uint4* sl = (const uint4*)(Bl + col0*136);
        uint4* th = (uint4*)(smem+GA_BH);
        uint4* tl = (uint4*)(smem+GA_BL);
        #pragma unroll
        for (int q=0;q<9;q++){
            int i = tid + q*256;
            if (i < 2176){ th[i]=sh[i]; tl[i]=sl[i]; }
        }
    }

    const int a_r = lane & 15, a_c = (lane & 16) >> 1;
    const int b4_r = (lane & 7) + ((lane & 16) >> 1);   // +8 rows for lanes 16..31
    const int b4_c = lane & 8;
    const int q = lane & 3, gq = lane >> 2;

    for (int rt=0; rt<4; rt++){
        const int row0 = (blockIdx.x*4+rt)*128;
        __syncthreads();
        for (int i=tid;i<4096;i+=256){
            int m = i>>5, k4 = (i&31)*4;
            float4 v = *(const float4*)&h[(row0+m)*HID_ + k4];
            __nv_bfloat162 hh, ll;
            bsplit(v.x, hh.x, ll.x); bsplit(v.y, hh.y, ll.y);
            *(__nv_bfloat162*)&ah_s[m*136+k4]   = hh;
            *(__nv_bfloat162*)&al_s[m*136+k4]   = ll;
            bsplit(v.z, hh.x, ll.x); bsplit(v.w, hh.y, ll.y);
            *(__nv_bfloat162*)&ah_s[m*136+k4+2] = hh;
            *(__nv_bfloat162*)&al_s[m*136+k4+2] = ll;
        }
        __syncthreads();

        float acc[16][4];
        #pragma unroll
        for (int i=0;i<16;i++){ acc[i][0]=0.f; acc[i][1]=0.f; acc[i][2]=0.f; acc[i][3]=0.f; }
        #pragma unroll
        for (int kk=0;kk<8;kk++){
            const int k0 = kk*16;
            uint32_t aaddr = sb + GA_AH + ((m0+a_r)*136 + k0 + a_c)*2;
            unsigned ahf[4], alf[4];
            ldsm4(ahf, aaddr);
            ldsm4(alf, aaddr + (GA_AL-GA_AH));
            #pragma unroll
            for (int ntp=0;ntp<8;ntp++){
                uint32_t baddr = sb + GA_BH + ((ntp*16+b4_r)*136 + k0 + b4_c)*2;
                unsigned bh[4], bl[4];
                ldsm4(bh, baddr);
                ldsm4(bl, baddr + (GA_BL-GA_BH));
                float* a0 = acc[ntp*2], *a1 = acc[ntp*2+1];
                mma_bf16(a0, ahf, bh[0], bh[1]);
                mma_bf16(a0, ahf, bl[0], bl[1]);
                mma_bf16(a0, alf, bh[0], bh[1]);
                mma_bf16(a1, ahf, bh[2], bh[3]);
                mma_bf16(a1, ahf, bl[2], bl[3]);
                mma_bf16(a1, alf, bh[2], bh[3]);
            }
        }
        #pragma unroll
        for (int half=0; half<2; half++){
            int row = row0 + m0 + gq + half*8;
            #pragma unroll
            for (int nt=0;nt<16;nt++){
                int col = col0 + nt*8 + q*2;
                *(float2*)&C[row*HD+col] =
                    make_float2(acc[nt][half*2], acc[nt][half*2+1]);
            }
        }
        if (blockIdx.z==0){
            #pragma unroll
            for (int half=0; half<2; half++){
                int row = row0 + m0 + gq + half*8;
                float pl=0.f, pr=0.f;
                #pragma unroll
                for (int nt=0;nt<16;nt++){
                    int col = nt*8 + q*2;
                    float v0 = acc[nt][half*2], v1 = acc[nt][half*2+1];
                    pl += v0*s_al[col] + v1*s_al[col+1];
                    pr += v0*s_ar[col] + v1*s_ar[col+1];
                }
                pl += __shfl_xor_sync(0xffffffffu, pl, 1);
                pl += __shfl_xor_sync(0xffffffffu, pl, 2);
                pr += __shfl_xor_sync(0xffffffffu, pr, 1);
                pr += __shfl_xor_sync(0xffffffffu, pr, 2);
                if (q==0){
                    g_el[row*NH + blockIdx.y] = pl;
                    g_er[row*NH + blockIdx.y] = pr;
                }
            }
        }
    }
}

// ---------------- merged edge pass + CSR fill --------------------------------
__global__ __launch_bounds__(256) void k_edgefill(const float* __restrict__ e,
        const int* __restrict__ src, const int* __restrict__ dst,
        const float* __restrict__ W_fe, const float* __restrict__ attn_e){
    __shared__ float ce[NH];
    int wid = threadIdx.x>>5, lane = threadIdx.x&31;
    if (wid < NH){
        float p = 0.f;
        #pragma unroll
        for (int q=0;q<4;q++){
            int d = lane + q*32;
            p += W_fe[wid*HDIM+d]*attn_e[wid*HDIM+d];
        }
        #pragma unroll
        for (int off=16; off; off>>=1) p += __shfl_xor_sync(0xffffffffu, p, off);
        if (lane==0) ce[wid]=p;
    }
    __syncthreads();
    int ei = blockIdx.x*256 + threadIdx.x;
    if (ei >= N_EDGES) return;
    int s = src[ei], d = dst[ei];
    float ev = e[ei];
    float4 els = ((const float4*)g_el)[s];
    float4 erd = ((const float4*)g_er)[d];
    float sc[4];
    sc[0] = els.x + erd.x + ev*ce[0];
    sc[1] = els.y + erd.y + ev*ce[1];
    sc[2] = els.z + erd.z + ev*ce[2];
    sc[3] = els.w + erd.w + ev*ce[3];
    int pos = g_rowptr[d] + atomicAdd(&g_cursor[d], 1);
    g_esrc[pos] = s;
    #pragma unroll
    for (int hh=0;hh<4;hh++){
        float v = sc[hh];
        v = v > 0.f ? v : SLOPE_*v;
        float wv = expf(v);
        atomicAdd(&g_z[d*NH+hh], wv);
        g_wsH[hh*N_EDGES+pos] = wv;
    }
}

// ---------------- CSR scan ----------------------------------------------------
__global__ __launch_bounds__(1024) void k_scan(){
    __shared__ int sm[1024];
    int t = threadIdx.x;
    int base = t*32;
    int s = 0;
    #pragma unroll
    for (int i=0;i<32;i++) s += g_deg[base+i];
    sm[t]=s; __syncthreads();
    for (int off=1; off<1024; off<<=1){
        int v = (t>=off)? sm[t-off] : 0;
        __syncthreads();
        if (t>=off) sm[t]+=v;
        __syncthreads();
    }
    int run = sm[t]-s;
    for (int i=0;i<32;i++){ g_rowptr[base+i]=run; run += g_deg[base+i]; }
    if (t==1023) g_rowptr[N_NODES]=run;
}

// ---------------- aggregation ---------------------------------------------------
__global__ __launch_bounds__(256) void k_agg(const float* __restrict__ gat_bias){
    int wid = threadIdx.x>>5, lane = threadIdx.x&31;
    int gw = blockIdx.x*8 + wid;
    int n = gw>>2, hh = gw&3;
    int beg = g_rowptr[n], end = g_rowptr[n+1];
    float zz = g_z[n*NH+hh];
    float zi = zz > 0.f ? 1.f/zz : 1.f;
    float4 acc = make_float4(0,0,0,0);
    const float4* ft4 = (const float4*)g_ft;
    const float* wp = g_wsH + hh*N_EDGES;
    int i = beg;
    for (; i+2<=end; i+=2){
        float w0 = wp[i],     w1 = wp[i+1];
        int   s0 = g_esrc[i], s1 = g_esrc[i+1];
        float4 v0 = ft4[s0*128 + hh*32 + lane];
        float4 v1 = ft4[s1*128 + hh*32 + lane];
        acc.x = fmaf(w0, v0.x, fmaf(w1, v1.x, acc.x));
        acc.y = fmaf(w0, v0.y, fmaf(w1, v1.y, acc.y));
        acc.z = fmaf(w0, v0.z, fmaf(w1, v1.z, acc.z));
        acc.w = fmaf(w0, v0.w, fmaf(w1, v1.w, acc.w));
    }
    if (i < end){
        float w0 = wp[i];
        int s0 = g_esrc[i];
        float4 v0 = ft4[s0*128 + hh*32 + lane];
        acc.x = fmaf(w0, v0.x, acc.x);
        acc.y = fmaf(w0, v0.y, acc.y);
        acc.z = fmaf(w0, v0.z, acc.z);
        acc.w = fmaf(w0, v0.w, acc.w);
    }
    int base = n*HD + hh*HDIM + lane*4;
    float4 r  = *(const float4*)&g_res[base];
    float4 bv = *(const float4*)&gat_bias[hh*HDIM + lane*4];
    float4 o;
    o.x = fmaxf(acc.x*zi + r.x + bv.x, 0.f);
    o.y = fmaxf(acc.y*zi + r.y + bv.y, 0.f);
    o.z = fmaxf(acc.z*zi + r.z + bv.z, 0.f);
    o.w = fmaxf(acc.w*zi + r.w + bv.w, 0.f);
    *(float4*)&g_res[base] = o;
}

// ---------------- MHA via mma + relu + residual + LN1 -----------------------
__global__ __launch_bounds__(256,1) void k_mha_mma(const float* __restrict__ bm,
        const float* __restrict__ h0, const float* __restrict__ g1,
        const float* __restrict__ be1){
    extern __shared__ char smem[];
    __nv_bfloat16* ah_s = (__nv_bfloat16*)(smem+GA_AH);
    __nv_bfloat16* al_s = (__nv_bfloat16*)(smem+GA_AL);
    const uint32_t sb = smem_u32(smem);
    const int tid = threadIdx.x, lane = tid&31, w = tid>>5;
    const int m0 = w*16, row0 = blockIdx.x*128;

    const int a_r = lane & 15, a_c = (lane & 16) >> 1;
    const int b4_r = (lane & 7) + ((lane & 16) >> 1);
    const int b4_c = lane & 8;
    const int q = lane & 3, gq = lane >> 2;

    float acc[16][4];
    #pragma unroll
    for (int i=0;i<16;i++){ acc[i][0]=0.f; acc[i][1]=0.f; acc[i][2]=0.f; acc[i][3]=0.f; }

    for (int c=0; c<4; c++){
        __syncthreads();
        for (int i=tid;i<4096;i+=256){
            int m = i>>5, k4 = (i&31)*4;
            float4 v = *(const float4*)&g_res[(row0+m)*HD + c*128 + k4];
            __nv_bfloat162 hh, ll;
            bsplit(v.x, hh.x, ll.x); bsplit(v.y, hh.y, ll.y);
            *(__nv_bfloat162*)&ah_s[m*136+k4]   = hh;
            *(__nv_bfloat162*)&al_s[m*136+k4]   = ll;
            bsplit(v.z, hh.x, ll.x); bsplit(v.w, hh.y, ll.y);
            *(__nv_bfloat162*)&ah_s[m*136+k4+2] = hh;
            *(__nv_bfloat162*)&al_s[m*136+k4+2] = ll;
        }
        {
            const uint4* sh = (const uint4*)(g_wmth + c*128*136);
            const uint4* sl = (const uint4*)(g_wmtl + c*128*136);
            uint4* th = (uint4*)(smem+GA_BH);
            uint4* tl = (uint4*)(smem+GA_BL);
            #pragma unroll
            for (int qq=0;qq<9;qq++){
                int i = tid + qq*256;
                if (i < 2176){ th[i]=sh[i]; tl[i]=sl[i]; }
            }
        }
        __syncthreads();
        #pragma unroll
        for (int kk=0;kk<8;kk++){
            const int k0 = kk*16;
            uint32_t aaddr = sb + GA_AH + ((m0+a_r)*136 + k0 + a_c)*2;
            unsigned ahf[4], alf[4];
            ldsm4(ahf, aaddr);
            ldsm4(alf, aaddr + (GA_AL-GA_AH));
            #pragma unroll
            for (int ntp=0;ntp<8;ntp++){
                uint32_t baddr = sb + GA_BH + ((ntp*16+b4_r)*136 + k0 + b4_c)*2;
                unsigned bh[4], bl[4];
                ldsm4(bh, baddr);
                ldsm4(bl, baddr + (GA_BL-GA_BH));
                float* a0 = acc[ntp*2], *a1 = acc[ntp*2+1];
                mma_bf16(a0, ahf, bh[0], bh[1]);
                mma_bf16(a0, ahf, bl[0], bl[1]);
                mma_bf16(a0, alf, bh[0], bh[1]);
                mma_bf16(a1, ahf, bh[2], bh[3]);
                mma_bf16(a1, ahf, bl[2], bl[3]);
                mma_bf16(a1, alf, bh[2], bh[3]);
            }
        }
    }

    #pragma unroll
    for (int half=0; half<2; half++){
        int row = row0 + m0 + gq + half*8;
        float tv[32], s1=0.f, s2=0.f;
        #pragma unroll
        for (int nt=0;nt<16;nt++){
            int col = nt*8 + q*2;
            float t0 = fmaxf(acc[nt][half*2+0] + bm[col],   0.f) + h0[row*HID_+col];
            float t1 = fmaxf(acc[nt][half*2+1] + bm[col+1], 0.f) + h0[row*HID_+col+1];
            tv[nt*2]=t0; tv[nt*2+1]=t1;
            s1 += t0+t1; s2 += t0*t0+t1*t1;
        }
        s1 += __shfl_xor_sync(0xffffffffu, s1, 1); s2 += __shfl_xor_sync(0xffffffffu, s2, 1);
        s1 += __shfl_xor_sync(0xffffffffu, s1, 2); s2 += __shfl_xor_sync(0xffffffffu, s2, 2);
        float mean = s1*(1.f/HID_);
        float var  = s2*(1.f/HID_) - mean*mean;
        float rs   = rsqrtf(var + EPS_);
        #pragma unroll
        for (int nt=0;nt<16;nt++){
            int col = nt*8 + q*2;
            g_x1[row*HID_+col]   = (tv[nt*2]  -mean)*rs*g1[col]   + be1[col];
            g_x1[row*HID_+col+1] = (tv[nt*2+1]-mean)*rs*g1[col+1] + be1[col+1];
        }
    }
}

// ---------------- FFN via mma.sync (bf16 hi/lo split) + residual + LN2 ------
#define SM_XS_H 0
#define SM_XS_L 34816
#define SM_W1H  69632
#define SM_W1L  87040
#define SM_W2H  104448
#define SM_W2L  122880
#define SM_MIDH 141312
#define SM_MIDL 159744
#define SMEM_FFN 178176

__global__ __launch_bounds__(256,1) void k_ffn_mma(const float* __restrict__ b1v,
        const float* __restrict__ b2v, const float* __restrict__ g2,
        const float* __restrict__ be2, float* __restrict__ out){
    extern __shared__ char smem[];
    __nv_bfloat16* xs_h = (__nv_bfloat16*)(smem+SM_XS_H);
    __nv_bfloat16* xs_l = (__nv_bfloat16*)(smem+SM_XS_L);
    __nv_bfloat16* mid_h= (__nv_bfloat16*)(smem+SM_MIDH);
    __nv_bfloat16* mid_l= (__nv_bfloat16*)(smem+SM_MIDL);
    const uint32_t sb = smem_u32(smem);
    const int tid = threadIdx.x, lane = tid&31, w = tid>>5;
    const int row0 = blockIdx.x*128, m0 = w*16;

    for (int i=tid;i<128*128;i+=256){
        int m=i>>7, k=i&127;
        float v = g_x1[(row0+m)*HID_ + k];
        __nv_bfloat16 hv, lv; bsplit(v, hv, lv);
        xs_h[m*136+k] = hv;
        xs_l[m*136+k] = lv;
    }

    float acc2[16][4];
    #pragma unroll
    for (int i=0;i<16;i++){ acc2[i][0]=0.f; acc2[i][1]=0.f; acc2[i][2]=0.f; acc2[i][3]=0.f; }

    const int a_r = lane & 15, a_c = (lane & 16) >> 1;
    const int b4_r = (lane & 7) + ((lane & 16) >> 1);
    const int b4_c = lane & 8;
    const int q = lane & 3, gq = lane >> 2;

    for (int c=0; c<32; c++){
        __syncthreads();
        {
            const uint4* s1h = (const uint4*)(g_w1th + c*64*136);
            const uint4* s1l = (const uint4*)(g_w1tl + c*64*136);
            const uint4* s2h = (const uint4*)(g_w2th + c*128*72);
            const uint4* s2l = (const uint4*)(g_w2tl + c*128*72);
            uint4* t1h = (uint4*)(smem+SM_W1H); uint4* t1l = (uint4*)(smem+SM_W1L);
            uint4* t2h = (uint4*)(smem+SM_W2H); uint4* t2l = (uint4*)(smem+SM_W2L);
            for (int i=tid;i<1088;i+=256){ t1h[i]=s1h[i]; t1l[i]=s1l[i]; }
            for (int i=tid;i<1152;i+=256){ t2h[i]=s2h[i]; t2l[i]=s2l[i]; }
        }
        __syncthreads();

        float acc1[8][4];
        #pragma unroll
        for (int i=0;i<8;i++){ acc1[i][0]=0.f; acc1[i][1]=0.f; acc1[i][2]=0.f; acc1[i][3]=0.f; }
        #pragma unroll
        for (int kk=0;kk<8;kk++){
            const int k0 = kk*16;
            uint32_t aaddr = sb + SM_XS_H + ((m0+a_r)*136 + k0 + a_c)*2;
            unsigned ah[4], al[4];
            ldsm4(ah, aaddr);
            ldsm4(al, aaddr + (SM_XS_L - SM_XS_H));
            #pragma unroll
            for (int ntp=0;ntp<4;ntp++){
                uint32_t baddr = sb + SM_W1H + ((ntp*16+b4_r)*136 + k0 + b4_c)*2;
                unsigned bh[4], bl[4];
                ldsm4(bh, baddr);
                ldsm4(bl, baddr + (SM_W1L - SM_W1H));
                float* a0 = acc1[ntp*2], *a1 = acc1[ntp*2+1];
                mma_bf16(a0, ah, bh[0], bh[1]);
                mma_bf16(a0, ah, bl[0], bl[1]);
                mma_bf16(a0, al, bh[0], bh[1]);
                mma_bf16(a1, ah, bh[2], bh[3]);
                mma_bf16(a1, ah, bl[2], bl[3]);
                mma_bf16(a1, al, bh[2], bh[3]);
            }
        }
        {
            const int r1 = m0 + gq, r2 = r1 + 8;
            #pragma unroll
            for (int nt=0;nt<8;nt++){
                int col = nt*8 + q*2;
                float bb0 = b1v[c*64+col], bb1 = b1v[c*64+col+1];
                float v0 = fmaxf(acc1[nt][0]+bb0, 0.f);
                float v1 = fmaxf(acc1[nt][1]+bb1, 0.f);
                float v2 = fmaxf(acc1[nt][2]+bb0, 0.f);
                float v3 = fmaxf(acc1[nt][3]+bb1, 0.f);
                __nv_bfloat162 hh, ll;
                bsplit(v0, hh.x, ll.x); bsplit(v1, hh.y, ll.y);
                *(__nv_bfloat162*)&mid_h[r1*72+col]=hh;
                *(__nv_bfloat162*)&mid_l[r1*72+col]=ll;
                bsplit(v2, hh.x, ll.x); bsplit(v3, hh.y, ll.y);
                *(__nv_bfloat162*)&mid_h[r2*72+col]=hh;
                *(__nv_bfloat162*)&mid_l[r2*72+col]=ll;
            }
        }
        __syncthreads();

        #pragma unroll
        for (int kk=0;kk<4;kk++){
            const int k0 = kk*16;
            uint32_t aaddr = sb + SM_MIDH + ((m0+a_r)*72 + k0 + a_c)*2;
            unsigned ah[4], al[4];
            ldsm4(ah, aaddr);
            ldsm4(al, aaddr + (SM_MIDL - SM_MIDH));
            #pragma unroll
            for (int ntp=0;ntp<8;ntp++){
                uint32_t baddr = sb + SM_W2H + ((ntp*16+b4_r)*72 + k0 + b4_c)*2;
                unsigned bh[4], bl[4];
                ldsm4(bh, baddr);
                ldsm4(bl, baddr + (SM_W2L - SM_W2H));
                float* a0 = acc2[ntp*2], *a1 = acc2[ntp*2+1];
                mma_bf16(a0, ah, bh[0], bh[1]);
                mma_bf16(a0, ah, bl[0], bl[1]);
                mma_bf16(a0, al, bh[0], bh[1]);
                mma_bf16(a1, ah, bh[2], bh[3]);
                mma_bf16(a1, ah, bl[2], bl[3]);
                mma_bf16(a1, al, bh[2], bh[3]);
            }
        }
    }

    #pragma unroll
    for (int half=0; half<2; half++){
        int grow = row0 + m0 + gq + half*8;
        float tv[32], s1=0.f, s2=0.f;
        #pragma unroll
        for (int nt=0;nt<16;nt++){
            int col = nt*8 + q*2;
            float t0 = acc2[nt][half*2+0] + b2v[col]   + g_x1[grow*HID_+col];
            float t1 = acc2[nt][half*2+1] + b2v[col+1] + g_x1[grow*HID_+col+1];
            tv[nt*2]=t0; tv[nt*2+1]=t1;
            s1 += t0+t1; s2 += t0*t0+t1*t1;
        }
        s1 += __shfl_xor_sync(0xffffffffu, s1, 1); s2 += __shfl_xor_sync(0xffffffffu, s2, 1);
        s1 += __shfl_xor_sync(0xffffffffu, s1, 2); s2 += __shfl_xor_sync(0xffffffffu, s2, 2);
        float mean = s1*(1.f/HID_);
        float var  = s2*(1.f/HID_) - mean*mean;
        float rs   = rsqrtf(var + EPS_);
        #pragma unroll
        for (int nt=0;nt<16;nt++){
            int col = nt*8 + q*2;
            out[grow*HID_+col]   = (tv[nt*2]  -mean)*rs*g2[col]   + be2[col];
            out[grow*HID_+col+1] = (tv[nt*2+1]-mean)*rs*g2[col+1] + be2[col+1];
        }
    }
}

// ---------------- launch ----------------------------------------------------
extern "C" void kernel_launch(void* const* d_in, const int* in_sizes, int n_in,
                              void* d_out, int out_size){
    int o = (in_sizes[4] == 1) ? 1 : 0;
    const float* h       = (const float*)d_in[0];
    const float* e       = (const float*)d_in[1];
    const int*   src     = (const int*)  d_in[2];
    const int*   dst     = (const int*)  d_in[3];
    const float* W_fc    = (const float*)d_in[4+o];
    const float* attn_l  = (const float*)d_in[5+o];
    const float* attn_r  = (const float*)d_in[6+o];
    const float* W_fe    = (const float*)d_in[7+o];
    const float* attn_e  = (const float*)d_in[8+o];
    const float* W_res   = (const float*)d_in[9+o];
    const float* gatb    = (const float*)d_in[10+o];
    const float* W_mha   = (const float*)d_in[11+o];
    const float* b_mha   = (const float*)d_in[12+o];
    const float* n1_g    = (const float*)d_in[13+o];
    const float* n1_b    = (const float*)d_in[14+o];
    const float* n2_g    = (const float*)d_in[15+o];
    const float* n2_b    = (const float*)d_in[16+o];
    const float* W1      = (const float*)d_in[17+o];
    const float* b1      = (const float*)d_in[18+o];
    const float* W2      = (const float*)d_in[19+o];
    const float* b2      = (const float*)d_in[20+o];
    float* out = (float*)d_out;

    cudaFuncSetAttribute(k_ffn_mma,  cudaFuncAttributeMaxDynamicSharedMemorySize, SMEM_FFN);
    cudaFuncSetAttribute(k_gemmA_mma,cudaFuncAttributeMaxDynamicSharedMemorySize, SMEM_GA);
    cudaFuncSetAttribute(k_mha_mma,  cudaFuncAttributeMaxDynamicSharedMemorySize, SMEM_GA);

    k_init<<<512,256>>>();
    k_prep<<<1024,256>>>(W1, W2, W_fc, W_res, W_mha);
    k_deg<<<N_EDGES/256,256>>>(dst);
    dim3 gA(64, 4, 2);
    k_gemmA_mma<<<gA,256,SMEM_GA>>>(h, attn_l, attn_r);
    k_scan<<<1,1024>>>();
    k_edgefill<<<N_EDGES/256,256>>>(e, src, dst, W_fe, attn_e);
    k_agg<<<N_NODES*NH/8,256>>>(gatb);
    k_mha_mma<<<N_NODES/128,256,SMEM_GA>>>(b_mha, h, n1_g, n1_b);
    k_ffn_mma<<<N_NODES/128,256,SMEM_FFN>>>(b1, b2, n2_g, n2_b, out);
}

// round 8
// speedup vs baseline: 1.6388x; 1.0757x over previous
#include <cuda_runtime.h>
#include <cuda_bf16.h>
#include <cstdint>

#define N_NODES 32768
#define N_EDGES 524288
#define NH      4
#define HDIM    128
#define HD      512
#define HID_    128
#define DFF_    2048
#define SLOPE_  0.2f
#define EPS_    1e-5f

// ---------------- scratch ----------------------------------------------------
__device__ float    g_ft [N_NODES*HD];
__device__ float    g_res[N_NODES*HD];
__device__ float    g_el [N_NODES*NH];
__device__ float    g_er [N_NODES*NH];
__device__ float    g_z  [N_NODES*NH];
__device__ int      g_deg[N_NODES];
__device__ int      g_cursor[N_NODES];
__device__ int      g_rowptr[N_NODES+1];
__device__ int      g_esrc[N_EDGES];        // CSR-sorted src
__device__ float    g_wsH[NH*N_EDGES];      // CSR-sorted weights, head-major
__device__ float    g_x1 [N_NODES*HID_];

// pre-split hi/lo bf16 transposed weights ([n][k] padded rows)
__device__ __align__(16) __nv_bfloat16 g_w1th[32*64*136];
__device__ __align__(16) __nv_bfloat16 g_w1tl[32*64*136];
__device__ __align__(16) __nv_bfloat16 g_w2th[32*128*72];
__device__ __align__(16) __nv_bfloat16 g_w2tl[32*128*72];
__device__ __align__(16) __nv_bfloat16 g_wfth[512*136];   // W_fc^T
__device__ __align__(16) __nv_bfloat16 g_wftl[512*136];
__device__ __align__(16) __nv_bfloat16 g_wrth[512*136];   // W_res^T
__device__ __align__(16) __nv_bfloat16 g_wrtl[512*136];
__device__ __align__(16) __nv_bfloat16 g_wmth[512*136];   // W_mha^T
__device__ __align__(16) __nv_bfloat16 g_wmtl[512*136];

// ---------------- helpers ------------------------------------------------------
__device__ __forceinline__ uint32_t smem_u32(const void* p){
    uint32_t a;
    asm("{ .reg .u64 t; cvta.to.shared.u64 t, %1; cvt.u32.u64 %0, t; }" : "=r"(a) : "l"(p));
    return a;
}
__device__ __forceinline__ void ldsm4(unsigned* r, uint32_t addr){
    asm volatile("ldmatrix.sync.aligned.m8n8.x4.shared.b16 {%0,%1,%2,%3}, [%4];"
        : "=r"(r[0]),"=r"(r[1]),"=r"(r[2]),"=r"(r[3]) : "r"(addr));
}
__device__ __forceinline__ void mma_bf16(float* c, const unsigned* a, unsigned b0, unsigned b1){
    asm volatile("mma.sync.aligned.m16n8k16.row.col.f32.bf16.bf16.f32 "
        "{%0,%1,%2,%3},{%4,%5,%6,%7},{%8,%9},{%0,%1,%2,%3};"
        : "+f"(c[0]),"+f"(c[1]),"+f"(c[2]),"+f"(c[3])
        : "r"(a[0]),"r"(a[1]),"r"(a[2]),"r"(a[3]),"r"(b0),"r"(b1));
}
__device__ __forceinline__ void bsplit(float v, __nv_bfloat16& hi, __nv_bfloat16& lo){
    hi = __float2bfloat16(v);
    lo = __float2bfloat16(v - __bfloat162float(hi));
}

// ---------------- init ------------------------------------------------------
__global__ void k_init(){
    int i = blockIdx.x*256 + threadIdx.x;
    g_z[i] = 0.f;
    if (i < N_NODES){ g_deg[i] = 0; g_cursor[i] = 0; }
}

// ---------------- prep: weights -> hi/lo bf16 transposed tiles --------------
__global__ void k_prep(const float* __restrict__ W1, const float* __restrict__ W2,
                       const float* __restrict__ Wfc, const float* __restrict__ Wres,
                       const float* __restrict__ Wm){
    int i = blockIdx.x*256 + threadIdx.x;    // 0 .. 262143
    {   // W1 [k=128][n=2048]
        int k = i >> 11, n = i & 2047;
        __nv_bfloat16 hv, lv; bsplit(W1[i], hv, lv);
        int c = n >> 6, nn = n & 63;
        g_w1th[(c*64+nn)*136 + k] = hv;
        g_w1tl[(c*64+nn)*136 + k] = lv;
    }
    {   // W2 [k2=2048][n=128]
        int k2 = i >> 7, n = i & 127;
        __nv_bfloat16 hv, lv; bsplit(W2[i], hv, lv);
        int c = k2 >> 6, kk = k2 & 63;
        g_w2th[(c*128+n)*72 + kk] = hv;
        g_w2tl[(c*128+n)*72 + kk] = lv;
    }
    if (i < 65536){
        {   // Wfc/Wres [k=128][n=512]
            int k = i >> 9, n = i & 511;
            __nv_bfloat16 hv, lv;
            bsplit(Wfc[i], hv, lv);
            g_wfth[n*136 + k] = hv; g_wftl[n*136 + k] = lv;
            bsplit(Wres[i], hv, lv);
            g_wrth[n*136 + k] = hv; g_wrtl[n*136 + k] = lv;
        }
        {   // Wm [k2=512][n=128] -> chunk-major [c][n][136]
            int k2 = i >> 7, n = i & 127;
            __nv_bfloat16 hv, lv; bsplit(Wm[i], hv, lv);
            int c = k2 >> 7, kk = k2 & 127;
            g_wmth[(c*128+n)*136 + kk] = hv;
            g_wmtl[(c*128+n)*136 + kk] = lv;
        }
    }
}

// ---------------- degree count ------------------------------------------------
__global__ __launch_bounds__(256) void k_deg(const int* __restrict__ dst){
    int ei = blockIdx.x*256 + threadIdx.x;
    if (ei < N_EDGES) atomicAdd(&g_deg[dst[ei]], 1);
}

// ---------------- GEMM A via mma, 512 threads (+fused el/er on z==0) --------
#define GA_AH 0
#define GA_AL 34816
#define GA_BH 69632
#define GA_BL 104448
#define SMEM_GA 139264

__global__ __launch_bounds__(512,1) void k_gemmA_mma(const float* __restrict__ h,
        const float* __restrict__ attn_l, const float* __restrict__ attn_r){
    extern __shared__ char smem[];
    __shared__ float s_al[128], s_ar[128];
    __shared__ float s_pl[128][2], s_pr[128][2];
    __nv_bfloat16* ah_s = (__nv_bfloat16*)(smem+GA_AH);
    __nv_bfloat16* al_s = (__nv_bfloat16*)(smem+GA_AL);
    const uint32_t sb = smem_u32(smem);
    const int tid = threadIdx.x, lane = tid&31, w = tid>>5;
    const int strip = w>>1, nh = w&1;
    const int m0 = strip*16, ncol0 = nh*64;
    const int col0 = blockIdx.y*128;
    const __nv_bfloat16* Bh = blockIdx.z ? g_wrth : g_wfth;
    const __nv_bfloat16* Bl = blockIdx.z ? g_wrtl : g_wftl;
    float* __restrict__ C = blockIdx.z ? g_res : g_ft;

    if (blockIdx.z==0 && tid<128){
        s_al[tid] = attn_l[col0+tid];
        s_ar[tid] = attn_r[col0+tid];
    }
    {   // load B tile
        const uint4* sh = (const uint4*)(Bh + col0*136);
        const uint4* sl = (const uint4*)(Bl + col0*136);
        uint4* th = (uint4*)(smem+GA_BH);
        uint4* tl = (uint4*)(smem+GA_BL);
        for (int i=tid;i<2176;i+=512){ th[i]=sh[i]; tl[i]=sl[i]; }
    }

    const int a_r = lane & 15, a_c = (lane & 16) >> 1;
    const int b4_r = (lane & 7) + ((lane & 16) >> 1);
    const int b4_c = lane & 8;
    const int q = lane & 3, gq = lane >> 2;

    for (int rt=0; rt<4; rt++){
        const int row0 = (blockIdx.x*4+rt)*128;
        __syncthreads();
        for (int i=tid;i<4096;i+=512){
            int m = i>>5, k4 = (i&31)*4;
            float4 v = *(const float4*)&h[(row0+m)*HID_ + k4];
            __nv_bfloat162 hh, ll;
            bsplit(v.x, hh.x, ll.x); bsplit(v.y, hh.y, ll.y);
            *(__nv_bfloat162*)&ah_s[m*136+k4]   = hh;
            *(__nv_bfloat162*)&al_s[m*136+k4]   = ll;
            bsplit(v.z, hh.x, ll.x); bsplit(v.w, hh.y, ll.y);
            *(__nv_bfloat162*)&ah_s[m*136+k4+2] = hh;
            *(__nv_bfloat162*)&al_s[m*136+k4+2] = ll;
        }
        __syncthreads();

        float acc[8][4];
        #pragma unroll
        for (int i=0;i<8;i++){ acc[i][0]=0.f; acc[i][1]=0.f; acc[i][2]=0.f; acc[i][3]=0.f; }
        #pragma unroll
        for (int kk=0;kk<8;kk++){
            const int k0 = kk*16;
            uint32_t aaddr = sb + GA_AH + ((m0+a_r)*136 + k0 + a_c)*2;
            unsigned ahf[4], alf[4];
            ldsm4(ahf, aaddr);
            ldsm4(alf, aaddr + (GA_AL-GA_AH));
            #pragma unroll
            for (int ntp=0;ntp<4;ntp++){
                uint32_t baddr = sb + GA_BH + ((ncol0+ntp*16+b4_r)*136 + k0 + b4_c)*2;
                unsigned bh[4], bl[4];
                ldsm4(bh, baddr);
                ldsm4(bl, baddr + (GA_BL-GA_BH));
                float* a0 = acc[ntp*2], *a1 = acc[ntp*2+1];
                mma_bf16(a0, ahf, bh[0], bh[1]);
                mma_bf16(a0, ahf, bl[0], bl[1]);
                mma_bf16(a0, alf, bh[0], bh[1]);
                mma_bf16(a1, ahf, bh[2], bh[3]);
                mma_bf16(a1, ahf, bl[2], bl[3]);
                mma_bf16(a1, alf, bh[2], bh[3]);
            }
        }
        #pragma unroll
        for (int half=0; half<2; half++){
            int row = row0 + m0 + gq + half*8;
            #pragma unroll
            for (int nt=0;nt<8;nt++){
                int col = col0 + ncol0 + nt*8 + q*2;
                *(float2*)&C[row*HD+col] =
                    make_float2(acc[nt][half*2], acc[nt][half*2+1]);
            }
        }
        if (blockIdx.z==0){
            #pragma unroll
            for (int half=0; half<2; half++){
                int rl = m0 + gq + half*8;
                float pl=0.f, pr=0.f;
                #pragma unroll
                for (int nt=0;nt<8;nt++){
                    int col = ncol0 + nt*8 + q*2;
                    float v0 = acc[nt][half*2], v1 = acc[nt][half*2+1];
                    pl += v0*s_al[col] + v1*s_al[col+1];
                    pr += v0*s_ar[col] + v1*s_ar[col+1];
                }
                pl += __shfl_xor_sync(0xffffffffu, pl, 1);
                pl += __shfl_xor_sync(0xffffffffu, pl, 2);
                pr += __shfl_xor_sync(0xffffffffu, pr, 1);
                pr += __shfl_xor_sync(0xffffffffu, pr, 2);
                if (q==0){ s_pl[rl][nh]=pl; s_pr[rl][nh]=pr; }
            }
            __syncthreads();
            if (tid<128){
                int row = row0 + tid;
                g_el[row*NH + blockIdx.y] = s_pl[tid][0]+s_pl[tid][1];
                g_er[row*NH + blockIdx.y] = s_pr[tid][0]+s_pr[tid][1];
            }
        }
    }
}

// ---------------- merged edge pass + CSR fill --------------------------------
__global__ __launch_bounds__(256) void k_edgefill(const float* __restrict__ e,
        const int* __restrict__ src, const int* __restrict__ dst,
        const float* __restrict__ W_fe, const float* __restrict__ attn_e){
    __shared__ float ce[NH];
    int wid = threadIdx.x>>5, lane = threadIdx.x&31;
    if (wid < NH){
        float p = 0.f;
        #pragma unroll
        for (int q=0;q<4;q++){
            int d = lane + q*32;
            p += W_fe[wid*HDIM+d]*attn_e[wid*HDIM+d];
        }
        #pragma unroll
        for (int off=16; off; off>>=1) p += __shfl_xor_sync(0xffffffffu, p, off);
        if (lane==0) ce[wid]=p;
    }
    __syncthreads();
    int ei = blockIdx.x*256 + threadIdx.x;
    if (ei >= N_EDGES) return;
    int s = src[ei], d = dst[ei];
    float ev = e[ei];
    float4 els = ((const float4*)g_el)[s];
    float4 erd = ((const float4*)g_er)[d];
    float sc[4];
    sc[0] = els.x + erd.x + ev*ce[0];
    sc[1] = els.y + erd.y + ev*ce[1];
    sc[2] = els.z + erd.z + ev*ce[2];
    sc[3] = els.w + erd.w + ev*ce[3];
    int pos = g_rowptr[d] + atomicAdd(&g_cursor[d], 1);
    g_esrc[pos] = s;
    #pragma unroll
    for (int hh=0;hh<4;hh++){
        float v = sc[hh];
        v = v > 0.f ? v : SLOPE_*v;
        float wv = expf(v);
        atomicAdd(&g_z[d*NH+hh], wv);
        g_wsH[hh*N_EDGES+pos] = wv;
    }
}

// ---------------- CSR scan ----------------------------------------------------
__global__ __launch_bounds__(1024) void k_scan(){
    __shared__ int sm[1024];
    int t = threadIdx.x;
    int base = t*32;
    int s = 0;
    #pragma unroll
    for (int i=0;i<32;i++) s += g_deg[base+i];
    sm[t]=s; __syncthreads();
    for (int off=1; off<1024; off<<=1){
        int v = (t>=off)? sm[t-off] : 0;
        __syncthreads();
        if (t>=off) sm[t]+=v;
        __syncthreads();
    }
    int run = sm[t]-s;
    for (int i=0;i<32;i++){ g_rowptr[base+i]=run; run += g_deg[base+i]; }
    if (t==1023) g_rowptr[N_NODES]=run;
}

// ---------------- aggregation ---------------------------------------------------
__global__ __launch_bounds__(256) void k_agg(const float* __restrict__ gat_bias){
    int wid = threadIdx.x>>5, lane = threadIdx.x&31;
    int gw = blockIdx.x*8 + wid;
    int n = gw>>2, hh = gw&3;
    int beg = g_rowptr[n], end = g_rowptr[n+1];
    float zz = g_z[n*NH+hh];
    float zi = zz > 0.f ? 1.f/zz : 1.f;
    float4 acc = make_float4(0,0,0,0);
    const float4* ft4 = (const float4*)g_ft;
    const float* wp = g_wsH + hh*N_EDGES;
    int i = beg;
    for (; i+2<=end; i+=2){
        float w0 = wp[i],     w1 = wp[i+1];
        int   s0 = g_esrc[i], s1 = g_esrc[i+1];
        float4 v0 = ft4[s0*128 + hh*32 + lane];
        float4 v1 = ft4[s1*128 + hh*32 + lane];
        acc.x = fmaf(w0, v0.x, fmaf(w1, v1.x, acc.x));
        acc.y = fmaf(w0, v0.y, fmaf(w1, v1.y, acc.y));
        acc.z = fmaf(w0, v0.z, fmaf(w1, v1.z, acc.z));
        acc.w = fmaf(w0, v0.w, fmaf(w1, v1.w, acc.w));
    }
    if (i < end){
        float w0 = wp[i];
        int s0 = g_esrc[i];
        float4 v0 = ft4[s0*128 + hh*32 + lane];
        acc.x = fmaf(w0, v0.x, acc.x);
        acc.y = fmaf(w0, v0.y, acc.y);
        acc.z = fmaf(w0, v0.z, acc.z);
        acc.w = fmaf(w0, v0.w, acc.w);
    }
    int base = n*HD + hh*HDIM + lane*4;
    float4 r  = *(const float4*)&g_res[base];
    float4 bv = *(const float4*)&gat_bias[hh*HDIM + lane*4];
    float4 o;
    o.x = fmaxf(acc.x*zi + r.x + bv.x, 0.f);
    o.y = fmaxf(acc.y*zi + r.y + bv.y, 0.f);
    o.z = fmaxf(acc.z*zi + r.z + bv.z, 0.f);
    o.w = fmaxf(acc.w*zi + r.w + bv.w, 0.f);
    *(float4*)&g_res[base] = o;
}

// ---------------- MHA via mma, 512 threads + relu + residual + LN1 ----------
__global__ __launch_bounds__(512,1) void k_mha_mma(const float* __restrict__ bm,
        const float* __restrict__ h0, const float* __restrict__ g1,
        const float* __restrict__ be1){
    extern __shared__ char smem[];
    __shared__ float s_s1[128][2], s_s2[128][2];
    __nv_bfloat16* ah_s = (__nv_bfloat16*)(smem+GA_AH);
    __nv_bfloat16* al_s = (__nv_bfloat16*)(smem+GA_AL);
    const uint32_t sb = smem_u32(smem);
    const int tid = threadIdx.x, lane = tid&31, w = tid>>5;
    const int strip = w>>1, nh = w&1;
    const int m0 = strip*16, ncol0 = nh*64;
    const int row0 = blockIdx.x*128;

    const int a_r = lane & 15, a_c = (lane & 16) >> 1;
    const int b4_r = (lane & 7) + ((lane & 16) >> 1);
    const int b4_c = lane & 8;
    const int q = lane & 3, gq = lane >> 2;

    float acc[8][4];
    #pragma unroll
    for (int i=0;i<8;i++){ acc[i][0]=0.f; acc[i][1]=0.f; acc[i][2]=0.f; acc[i][3]=0.f; }

    for (int c=0; c<4; c++){
        __syncthreads();
        for (int i=tid;i<4096;i+=512){
            int m = i>>5, k4 = (i&31)*4;
            float4 v = *(const float4*)&g_res[(row0+m)*HD + c*128 + k4];
            __nv_bfloat162 hh, ll;
            bsplit(v.x, hh.x, ll.x); bsplit(v.y, hh.y, ll.y);
            *(__nv_bfloat162*)&ah_s[m*136+k4]   = hh;
            *(__nv_bfloat162*)&al_s[m*136+k4]   = ll;
            bsplit(v.z, hh.x, ll.x); bsplit(v.w, hh.y, ll.y);
            *(__nv_bfloat162*)&ah_s[m*136+k4+2] = hh;
            *(__nv_bfloat162*)&al_s[m*136+k4+2] = ll;
        }
        {
            const uint4* sh = (const uint4*)(g_wmth + c*128*136);
            const uint4* sl = (const uint4*)(g_wmtl + c*128*136);
            uint4* th = (uint4*)(smem+GA_BH);
            uint4* tl = (uint4*)(smem+GA_BL);
            for (int i=tid;i<2176;i+=512){ th[i]=sh[i]; tl[i]=sl[i]; }
        }
        __syncthreads();
        #pragma unroll
        for (int kk=0;kk<8;kk++){
            const int k0 = kk*16;
            uint32_t aaddr = sb + GA_AH + ((m0+a_r)*136 + k0 + a_c)*2;
            unsigned ahf[4], alf[4];
            ldsm4(ahf, aaddr);
            ldsm4(alf, aaddr + (GA_AL-GA_AH));
            #pragma unroll
            for (int ntp=0;ntp<4;ntp++){
                uint32_t baddr = sb + GA_BH + ((ncol0+ntp*16+b4_r)*136 + k0 + b4_c)*2;
                unsigned bh[4], bl[4];
                ldsm4(bh, baddr);
                ldsm4(bl, baddr + (GA_BL-GA_BH));
                float* a0 = acc[ntp*2], *a1 = acc[ntp*2+1];
                mma_bf16(a0, ahf, bh[0], bh[1]);
                mma_bf16(a0, ahf, bl[0], bl[1]);
                mma_bf16(a0, alf, bh[0], bh[1]);
                mma_bf16(a1, ahf, bh[2], bh[3]);
                mma_bf16(a1, ahf, bl[2], bl[3]);
                mma_bf16(a1, alf, bh[2], bh[3]);
            }
        }
    }

    // epilogue: +bm, relu, +h0, LN1 (cross-warp-pair via smem) -> g_x1
    #pragma unroll
    for (int half=0; half<2; half++){
        int rl = m0 + gq + half*8;
        int row = row0 + rl;
        float tv[16], s1=0.f, s2=0.f;
        #pragma unroll
        for (int nt=0;nt<8;nt++){
            int col = ncol0 + nt*8 + q*2;
            float t0 = fmaxf(acc[nt][half*2+0] + bm[col],   0.f) + h0[row*HID_+col];
            float t1 = fmaxf(acc[nt][half*2+1] + bm[col+1], 0.f) + h0[row*HID_+col+1];
            tv[nt*2]=t0; tv[nt*2+1]=t1;
            s1 += t0+t1; s2 += t0*t0+t1*t1;
        }
        s1 += __shfl_xor_sync(0xffffffffu, s1, 1); s2 += __shfl_xor_sync(0xffffffffu, s2, 1);
        s1 += __shfl_xor_sync(0xffffffffu, s1, 2); s2 += __shfl_xor_sync(0xffffffffu, s2, 2);
        if (q==0){ s_s1[rl][nh]=s1; s_s2[rl][nh]=s2; }
        __syncthreads();
        float fs1 = s_s1[rl][0]+s_s1[rl][1];
        float fs2 = s_s2[rl][0]+s_s2[rl][1];
        float mean = fs1*(1.f/HID_);
        float var  = fs2*(1.f/HID_) - mean*mean;
        float rs   = rsqrtf(var + EPS_);
        #pragma unroll
        for (int nt=0;nt<8;nt++){
            int col = ncol0 + nt*8 + q*2;
            g_x1[row*HID_+col]   = (tv[nt*2]  -mean)*rs*g1[col]   + be1[col];
            g_x1[row*HID_+col+1] = (tv[nt*2+1]-mean)*rs*g1[col+1] + be1[col+1];
        }
        __syncthreads();
    }
}

// ---------------- FFN via mma, 512 threads + residual + LN2 ------------------
#define SM_XS_H 0
#define SM_XS_L 34816
#define SM_W1H  69632
#define SM_W1L  87040
#define SM_W2H  104448
#define SM_W2L  122880
#define SM_MIDH 141312
#define SM_MIDL 159744
#define SMEM_FFN 178176

__global__ __launch_bounds__(512,1) void k_ffn_mma(const float* __restrict__ b1v,
        const float* __restrict__ b2v, const float* __restrict__ g2,
        const float* __restrict__ be2, float* __restrict__ out){
    extern __shared__ char smem[];
    __shared__ float s_s1[128][2], s_s2[128][2];
    __nv_bfloat16* xs_h = (__nv_bfloat16*)(smem+SM_XS_H);
    __nv_bfloat16* xs_l = (__nv_bfloat16*)(smem+SM_XS_L);
    __nv_bfloat16* mid_h= (__nv_bfloat16*)(smem+SM_MIDH);
    __nv_bfloat16* mid_l= (__nv_bfloat16*)(smem+SM_MIDL);
    const uint32_t sb = smem_u32(smem);
    const int tid = threadIdx.x, lane = tid&31, w = tid>>5;
    const int strip = w>>1, nh = w&1;
    const int m0 = strip*16;
    const int row0 = blockIdx.x*128;

    for (int i=tid;i<128*128;i+=512){
        int m=i>>7, k=i&127;
        float v = g_x1[(row0+m)*HID_ + k];
        __nv_bfloat16 hv, lv; bsplit(v, hv, lv);
        xs_h[m*136+k] = hv;
        xs_l[m*136+k] = lv;
    }

    float acc2[8][4];
    #pragma unroll
    for (int i=0;i<8;i++){ acc2[i][0]=0.f; acc2[i][1]=0.f; acc2[i][2]=0.f; acc2[i][3]=0.f; }

    const int a_r = lane & 15, a_c = (lane & 16) >> 1;
    const int b4_r = (lane & 7) + ((lane & 16) >> 1);
    const int b4_c = lane & 8;
    const int q = lane & 3, gq = lane >> 2;

    for (int c=0; c<32; c++){
        __syncthreads();
        {
            const uint4* s1h = (const uint4*)(g_w1th + c*64*136);
            const uint4* s1l = (const uint4*)(g_w1tl + c*64*136);
            const uint4* s2h = (const uint4*)(g_w2th + c*128*72);
            const uint4* s2l = (const uint4*)(g_w2tl + c*128*72);
            uint4* t1h = (uint4*)(smem+SM_W1H); uint4* t1l = (uint4*)(smem+SM_W1L);
            uint4* t2h = (uint4*)(smem+SM_W2H); uint4* t2l = (uint4*)(smem+SM_W2L);
            for (int i=tid;i<1088;i+=512){ t1h[i]=s1h[i]; t1l[i]=s1l[i]; }
            for (int i=tid;i<1152;i+=512){ t2h[i]=s2h[i]; t2l[i]=s2l[i]; }
        }
        __syncthreads();

        // GEMM1: mid[128x64]; warp covers rows m0..+15, mid cols nh*32..+31
        float acc1[4][4];
        #pragma unroll
        for (int i=0;i<4;i++){ acc1[i][0]=0.f; acc1[i][1]=0.f; acc1[i][2]=0.f; acc1[i][3]=0.f; }
        #pragma unroll
        for (int kk=0;kk<8;kk++){
            const int k0 = kk*16;
            uint32_t aaddr = sb + SM_XS_H + ((m0+a_r)*136 + k0 + a_c)*2;
            unsigned ah[4], al[4];
            ldsm4(ah, aaddr);
            ldsm4(al, aaddr + (SM_XS_L - SM_XS_H));
            #pragma unroll
            for (int ntp=0;ntp<2;ntp++){
                uint32_t baddr = sb + SM_W1H + ((nh*32+ntp*16+b4_r)*136 + k0 + b4_c)*2;
                unsigned bh[4], bl[4];
                ldsm4(bh, baddr);
                ldsm4(bl, baddr + (SM_W1L - SM_W1H));
                float* a0 = acc1[ntp*2], *a1 = acc1[ntp*2+1];
                mma_bf16(a0, ah, bh[0], bh[1]);
                mma_bf16(a0, ah, bl[0], bl[1]);
                mma_bf16(a0, al, bh[0], bh[1]);
                mma_bf16(a1, ah, bh[2], bh[3]);
                mma_bf16(a1, ah, bl[2], bl[3]);
                mma_bf16(a1, al, bh[2], bh[3]);
            }
        }
        {
            const int r1 = m0 + gq, r2 = r1 + 8;
            #pragma unroll
            for (int nt=0;nt<4;nt++){
                int col = nh*32 + nt*8 + q*2;
                float bb0 = b1v[c*64+col], bb1 = b1v[c*64+col+1];
                float v0 = fmaxf(acc1[nt][0]+bb0, 0.f);
                float v1 = fmaxf(acc1[nt][1]+bb1, 0.f);
                float v2 = fmaxf(acc1[nt][2]+bb0, 0.f);
                float v3 = fmaxf(acc1[nt][3]+bb1, 0.f);
                __nv_bfloat162 hh, ll;
                bsplit(v0, hh.x, ll.x); bsplit(v1, hh.y, ll.y);
                *(__nv_bfloat162*)&mid_h[r1*72+col]=hh;
                *(__nv_bfloat162*)&mid_l[r1*72+col]=ll;
                bsplit(v2, hh.x, ll.x); bsplit(v3, hh.y, ll.y);
                *(__nv_bfloat162*)&mid_h[r2*72+col]=hh;
                *(__nv_bfloat162*)&mid_l[r2*72+col]=ll;
            }
        }
        __syncthreads();

        // GEMM2: acc2 += mid[rows m0..][64] @ W2^T ; warp covers out cols nh*64..+63
        #pragma unroll
        for (int kk=0;kk<4;kk++){
            const int k0 = kk*16;
            uint32_t aaddr = sb + SM_MIDH + ((m0+a_r)*72 + k0 + a_c)*2;
            unsigned ah[4], al[4];
            ldsm4(ah, aaddr);
            ldsm4(al, aaddr + (SM_MIDL - SM_MIDH));
            #pragma unroll
            for (int ntp=0;ntp<4;ntp++){
                uint32_t baddr = sb + SM_W2H + ((nh*64+ntp*16+b4_r)*72 + k0 + b4_c)*2;
                unsigned bh[4], bl[4];
                ldsm4(bh, baddr);
                ldsm4(bl, baddr + (SM_W2L - SM_W2H));
                float* a0 = acc2[ntp*2], *a1 = acc2[ntp*2+1];
                mma_bf16(a0, ah, bh[0], bh[1]);
                mma_bf16(a0, ah, bl[0], bl[1]);
                mma_bf16(a0, al, bh[0], bh[1]);
                mma_bf16(a1, ah, bh[2], bh[3]);
                mma_bf16(a1, ah, bl[2], bl[3]);
                mma_bf16(a1, al, bh[2], bh[3]);
            }
        }
    }

    // epilogue: +b2 + residual + LN2 (cross-warp-pair via smem)
    #pragma unroll
    for (int half=0; half<2; half++){
        int rl = m0 + gq + half*8;
        int grow = row0 + rl;
        float tv[16], s1=0.f, s2=0.f;
        #pragma unroll
        for (int nt=0;nt<8;nt++){
            int col = nh*64 + nt*8 + q*2;
            float t0 = acc2[nt][half*2+0] + b2v[col]   + g_x1[grow*HID_+col];
            float t1 = acc2[nt][half*2+1] + b2v[col+1] + g_x1[grow*HID_+col+1];
            tv[nt*2]=t0; tv[nt*2+1]=t1;
            s1 += t0+t1; s2 += t0*t0+t1*t1;
        }
        s1 += __shfl_xor_sync(0xffffffffu, s1, 1); s2 += __shfl_xor_sync(0xffffffffu, s2, 1);
        s1 += __shfl_xor_sync(0xffffffffu, s1, 2); s2 += __shfl_xor_sync(0xffffffffu, s2, 2);
        if (q==0){ s_s1[rl][nh]=s1; s_s2[rl][nh]=s2; }
        __syncthreads();
        float fs1 = s_s1[rl][0]+s_s1[rl][1];
        float fs2 = s_s2[rl][0]+s_s2[rl][1];
        float mean = fs1*(1.f/HID_);
        float var  = fs2*(1.f/HID_) - mean*mean;
        float rs   = rsqrtf(var + EPS_);
        #pragma unroll
        for (int nt=0;nt<8;nt++){
            int col = nh*64 + nt*8 + q*2;
            out[grow*HID_+col]   = (tv[nt*2]  -mean)*rs*g2[col]   + be2[col];
            out[grow*HID_+col+1] = (tv[nt*2+1]-mean)*rs*g2[col+1] + be2[col+1];
        }
        __syncthreads();
    }
}

// ---------------- launch ----------------------------------------------------
extern "C" void kernel_launch(void* const* d_in, const int* in_sizes, int n_in,
                              void* d_out, int out_size){
    int o = (in_sizes[4] == 1) ? 1 : 0;
    const float* h       = (const float*)d_in[0];
    const float* e       = (const float*)d_in[1];
    const int*   src     = (const int*)  d_in[2];
    const int*   dst     = (const int*)  d_in[3];
    const float* W_fc    = (const float*)d_in[4+o];
    const float* attn_l  = (const float*)d_in[5+o];
    const float* attn_r  = (const float*)d_in[6+o];
    const float* W_fe    = (const float*)d_in[7+o];
    const float* attn_e  = (const float*)d_in[8+o];
    const float* W_res   = (const float*)d_in[9+o];
    const float* gatb    = (const float*)d_in[10+o];
    const float* W_mha   = (const float*)d_in[11+o];
    const float* b_mha   = (const float*)d_in[12+o];
    const float* n1_g    = (const float*)d_in[13+o];
    const float* n1_b    = (const float*)d_in[14+o];
    const float* n2_g    = (const float*)d_in[15+o];
    const float* n2_b    = (const float*)d_in[16+o];
    const float* W1      = (const float*)d_in[17+o];
    const float* b1      = (const float*)d_in[18+o];
    const float* W2      = (const float*)d_in[19+o];
    const float* b2      = (const float*)d_in[20+o];
    float* out = (float*)d_out;

    cudaFuncSetAttribute(k_ffn_mma,  cudaFuncAttributeMaxDynamicSharedMemorySize, SMEM_FFN);
    cudaFuncSetAttribute(k_gemmA_mma,cudaFuncAttributeMaxDynamicSharedMemorySize, SMEM_GA);
    cudaFuncSetAttribute(k_mha_mma,  cudaFuncAttributeMaxDynamicSharedMemorySize, SMEM_GA);

    k_init<<<512,256>>>();
    k_prep<<<1024,256>>>(W1, W2, W_fc, W_res, W_mha);
    k_deg<<<N_EDGES/256,256>>>(dst);
    dim3 gA(64, 4, 2);
    k_gemmA_mma<<<gA,512,SMEM_GA>>>(h, attn_l, attn_r);
    k_scan<<<1,1024>>>();
    k_edgefill<<<N_EDGES/256,256>>>(e, src, dst, W_fe, attn_e);
    k_agg<<<N_NODES*NH/8,256>>>(gatb);
    k_mha_mma<<<N_NODES/128,512,SMEM_GA>>>(b_mha, h, n1_g, n1_b);
    k_ffn_mma<<<N_NODES/128,512,SMEM_FFN>>>(b1, b2, n2_g, n2_b, out);
}

// round 9
// speedup vs baseline: 1.6684x; 1.0181x over previous
#include <cuda_runtime.h>
#include <cuda_bf16.h>
#include <cstdint>

#define N_NODES 32768
#define N_EDGES 524288
#define NH      4
#define HDIM    128
#define HD      512
#define HID_    128
#define DFF_    2048
#define SLOPE_  0.2f
#define EPS_    1e-5f

// ---------------- scratch ----------------------------------------------------
__device__ float    g_ft [N_NODES*HD];
__device__ float    g_res[N_NODES*HD];
__device__ float    g_el [N_NODES*NH];
__device__ float    g_er [N_NODES*NH];
__device__ float    g_z  [N_NODES*NH];
__device__ int      g_deg[N_NODES];
__device__ int      g_cursor[N_NODES];
__device__ int      g_rowptr[N_NODES+1];
__device__ int      g_esrc[N_EDGES];        // CSR-sorted src
__device__ float    g_wsH[NH*N_EDGES];      // CSR-sorted weights, head-major
__device__ float    g_x1 [N_NODES*HID_];

// pre-split hi/lo bf16 transposed weights ([n][k] padded rows)
__device__ __align__(16) __nv_bfloat16 g_w1th[32*64*136];
__device__ __align__(16) __nv_bfloat16 g_w1tl[32*64*136];
__device__ __align__(16) __nv_bfloat16 g_w2th[32*128*72];
__device__ __align__(16) __nv_bfloat16 g_w2tl[32*128*72];
__device__ __align__(16) __nv_bfloat16 g_wfth[512*136];   // W_fc^T
__device__ __align__(16) __nv_bfloat16 g_wftl[512*136];
__device__ __align__(16) __nv_bfloat16 g_wrth[512*136];   // W_res^T
__device__ __align__(16) __nv_bfloat16 g_wrtl[512*136];
__device__ __align__(16) __nv_bfloat16 g_wmth[512*136];   // W_mha^T
__device__ __align__(16) __nv_bfloat16 g_wmtl[512*136];

// ---------------- helpers ------------------------------------------------------
__device__ __forceinline__ uint32_t smem_u32(const void* p){
    uint32_t a;
    asm("{ .reg .u64 t; cvta.to.shared.u64 t, %1; cvt.u32.u64 %0, t; }" : "=r"(a) : "l"(p));
    return a;
}
__device__ __forceinline__ void ldsm4(unsigned* r, uint32_t addr){
    asm volatile("ldmatrix.sync.aligned.m8n8.x4.shared.b16 {%0,%1,%2,%3}, [%4];"
        : "=r"(r[0]),"=r"(r[1]),"=r"(r[2]),"=r"(r[3]) : "r"(addr));
}
__device__ __forceinline__ void mma_bf16(float* c, const unsigned* a, unsigned b0, unsigned b1){
    asm volatile("mma.sync.aligned.m16n8k16.row.col.f32.bf16.bf16.f32 "
        "{%0,%1,%2,%3},{%4,%5,%6,%7},{%8,%9},{%0,%1,%2,%3};"
        : "+f"(c[0]),"+f"(c[1]),"+f"(c[2]),"+f"(c[3])
        : "r"(a[0]),"r"(a[1]),"r"(a[2]),"r"(a[3]),"r"(b0),"r"(b1));
}
__device__ __forceinline__ void bsplit(float v, __nv_bfloat16& hi, __nv_bfloat16& lo){
    hi = __float2bfloat16(v);
    lo = __float2bfloat16(v - __bfloat162float(hi));
}

// ---------------- init ------------------------------------------------------
__global__ void k_init(){
    int i = blockIdx.x*256 + threadIdx.x;
    g_z[i] = 0.f;
    if (i < N_NODES){ g_deg[i] = 0; g_cursor[i] = 0; }
}

// ---------------- prep: weights -> hi/lo bf16 transposed tiles --------------
__global__ void k_prep(const float* __restrict__ W1, const float* __restrict__ W2,
                       const float* __restrict__ Wfc, const float* __restrict__ Wres,
                       const float* __restrict__ Wm){
    int i = blockIdx.x*256 + threadIdx.x;    // 0 .. 262143
    {   // W1 [k=128][n=2048]
        int k = i >> 11, n = i & 2047;
        __nv_bfloat16 hv, lv; bsplit(W1[i], hv, lv);
        int c = n >> 6, nn = n & 63;
        g_w1th[(c*64+nn)*136 + k] = hv;
        g_w1tl[(c*64+nn)*136 + k] = lv;
    }
    {   // W2 [k2=2048][n=128]
        int k2 = i >> 7, n = i & 127;
        __nv_bfloat16 hv, lv; bsplit(W2[i], hv, lv);
        int c = k2 >> 6, kk = k2 & 63;
        g_w2th[(c*128+n)*72 + kk] = hv;
        g_w2tl[(c*128+n)*72 + kk] = lv;
    }
    if (i < 65536){
        {   // Wfc/Wres [k=128][n=512]
            int k = i >> 9, n = i & 511;
            __nv_bfloat16 hv, lv;
            bsplit(Wfc[i], hv, lv);
            g_wfth[n*136 + k] = hv; g_wftl[n*136 + k] = lv;
            bsplit(Wres[i], hv, lv);
            g_wrth[n*136 + k] = hv; g_wrtl[n*136 + k] = lv;
        }
        {   // Wm [k2=512][n=128] -> chunk-major [c][n][136]
            int k2 = i >> 7, n = i & 127;
            __nv_bfloat16 hv, lv; bsplit(Wm[i], hv, lv);
            int c = k2 >> 7, kk = k2 & 127;
            g_wmth[(c*128+n)*136 + kk] = hv;
            g_wmtl[(c*128+n)*136 + kk] = lv;
        }
    }
}

// ---------------- degree count ------------------------------------------------
__global__ __launch_bounds__(256) void k_deg(const int* __restrict__ dst){
    int ei = blockIdx.x*256 + threadIdx.x;
    if (ei < N_EDGES) atomicAdd(&g_deg[dst[ei]], 1);
}

// ---------------- GEMM A via mma, 512 thr, BOTH weights per CTA -------------
// smem: A hi/lo 68KB + B_fc hi/lo 68KB + B_res hi/lo 68KB = 204KB
#define GA_AH  0
#define GA_AL  34816
#define GA_BFH 69632
#define GA_BFL 104448
#define GA_BRH 139264
#define GA_BRL 174080
#define SMEM_GA 208896
#define SMEM_MH 139264    // mha uses A + one B pair

__global__ __launch_bounds__(512,1) void k_gemmA_mma(const float* __restrict__ h,
        const float* __restrict__ attn_l, const float* __restrict__ attn_r){
    extern __shared__ char smem[];
    __shared__ float s_al[128], s_ar[128];
    __shared__ float s_pl[128][2], s_pr[128][2];
    __nv_bfloat16* ah_s = (__nv_bfloat16*)(smem+GA_AH);
    __nv_bfloat16* al_s = (__nv_bfloat16*)(smem+GA_AL);
    const uint32_t sb = smem_u32(smem);
    const int tid = threadIdx.x, lane = tid&31, w = tid>>5;
    const int strip = w>>1, nh = w&1;
    const int m0 = strip*16, ncol0 = nh*64;
    const int col0 = blockIdx.y*128;

    if (tid<128){
        s_al[tid] = attn_l[col0+tid];
        s_ar[tid] = attn_r[col0+tid];
    }
    {   // load both B tiles
        const uint4* fh = (const uint4*)(g_wfth + col0*136);
        const uint4* fl = (const uint4*)(g_wftl + col0*136);
        const uint4* rh = (const uint4*)(g_wrth + col0*136);
        const uint4* rl = (const uint4*)(g_wrtl + col0*136);
        uint4* tfh = (uint4*)(smem+GA_BFH);
        uint4* tfl = (uint4*)(smem+GA_BFL);
        uint4* trh = (uint4*)(smem+GA_BRH);
        uint4* trl = (uint4*)(smem+GA_BRL);
        for (int i=tid;i<2176;i+=512){
            tfh[i]=fh[i]; tfl[i]=fl[i]; trh[i]=rh[i]; trl[i]=rl[i];
        }
    }

    const int a_r = lane & 15, a_c = (lane & 16) >> 1;
    const int b4_r = (lane & 7) + ((lane & 16) >> 1);
    const int b4_c = lane & 8;
    const int q = lane & 3, gq = lane >> 2;

    for (int rt=0; rt<4; rt++){
        const int row0 = (blockIdx.x*4+rt)*128;
        __syncthreads();
        for (int i=tid;i<4096;i+=512){
            int m = i>>5, k4 = (i&31)*4;
            float4 v = *(const float4*)&h[(row0+m)*HID_ + k4];
            __nv_bfloat162 hh, ll;
            bsplit(v.x, hh.x, ll.x); bsplit(v.y, hh.y, ll.y);
            *(__nv_bfloat162*)&ah_s[m*136+k4]   = hh;
            *(__nv_bfloat162*)&al_s[m*136+k4]   = ll;
            bsplit(v.z, hh.x, ll.x); bsplit(v.w, hh.y, ll.y);
            *(__nv_bfloat162*)&ah_s[m*136+k4+2] = hh;
            *(__nv_bfloat162*)&al_s[m*136+k4+2] = ll;
        }
        __syncthreads();

        // ---- target 0: ft (+ el/er partials) ----
        {
            float acc[8][4];
            #pragma unroll
            for (int i=0;i<8;i++){ acc[i][0]=0.f; acc[i][1]=0.f; acc[i][2]=0.f; acc[i][3]=0.f; }
            #pragma unroll
            for (int kk=0;kk<8;kk++){
                const int k0 = kk*16;
                uint32_t aaddr = sb + GA_AH + ((m0+a_r)*136 + k0 + a_c)*2;
                unsigned ahf[4], alf[4];
                ldsm4(ahf, aaddr);
                ldsm4(alf, aaddr + (GA_AL-GA_AH));
                #pragma unroll
                for (int ntp=0;ntp<4;ntp++){
                    uint32_t baddr = sb + GA_BFH + ((ncol0+ntp*16+b4_r)*136 + k0 + b4_c)*2;
                    unsigned bh[4], bl[4];
                    ldsm4(bh, baddr);
                    ldsm4(bl, baddr + (GA_BFL-GA_BFH));
                    float* a0 = acc[ntp*2], *a1 = acc[ntp*2+1];
                    mma_bf16(a0, ahf, bh[0], bh[1]);
                    mma_bf16(a0, ahf, bl[0], bl[1]);
                    mma_bf16(a0, alf, bh[0], bh[1]);
                    mma_bf16(a1, ahf, bh[2], bh[3]);
                    mma_bf16(a1, ahf, bl[2], bl[3]);
                    mma_bf16(a1, alf, bh[2], bh[3]);
                }
            }
            #pragma unroll
            for (int half=0; half<2; half++){
                int row = row0 + m0 + gq + half*8;
                #pragma unroll
                for (int nt=0;nt<8;nt++){
                    int col = col0 + ncol0 + nt*8 + q*2;
                    *(float2*)&g_ft[row*HD+col] =
                        make_float2(acc[nt][half*2], acc[nt][half*2+1]);
                }
            }
            #pragma unroll
            for (int half=0; half<2; half++){
                int rl = m0 + gq + half*8;
                float pl=0.f, pr=0.f;
                #pragma unroll
                for (int nt=0;nt<8;nt++){
                    int col = ncol0 + nt*8 + q*2;
                    float v0 = acc[nt][half*2], v1 = acc[nt][half*2+1];
                    pl += v0*s_al[col] + v1*s_al[col+1];
                    pr += v0*s_ar[col] + v1*s_ar[col+1];
                }
                pl += __shfl_xor_sync(0xffffffffu, pl, 1);
                pl += __shfl_xor_sync(0xffffffffu, pl, 2);
                pr += __shfl_xor_sync(0xffffffffu, pr, 1);
                pr += __shfl_xor_sync(0xffffffffu, pr, 2);
                if (q==0){ s_pl[rl][nh]=pl; s_pr[rl][nh]=pr; }
            }
        }
        __syncthreads();
        if (tid<128){
            int row = row0 + tid;
            g_el[row*NH + blockIdx.y] = s_pl[tid][0]+s_pl[tid][1];
            g_er[row*NH + blockIdx.y] = s_pr[tid][0]+s_pr[tid][1];
        }

        // ---- target 1: res ----
        {
            float acc[8][4];
            #pragma unroll
            for (int i=0;i<8;i++){ acc[i][0]=0.f; acc[i][1]=0.f; acc[i][2]=0.f; acc[i][3]=0.f; }
            #pragma unroll
            for (int kk=0;kk<8;kk++){
                const int k0 = kk*16;
                uint32_t aaddr = sb + GA_AH + ((m0+a_r)*136 + k0 + a_c)*2;
                unsigned ahf[4], alf[4];
                ldsm4(ahf, aaddr);
                ldsm4(alf, aaddr + (GA_AL-GA_AH));
                #pragma unroll
                for (int ntp=0;ntp<4;ntp++){
                    uint32_t baddr = sb + GA_BRH + ((ncol0+ntp*16+b4_r)*136 + k0 + b4_c)*2;
                    unsigned bh[4], bl[4];
                    ldsm4(bh, baddr);
                    ldsm4(bl, baddr + (GA_BRL-GA_BRH));
                    float* a0 = acc[ntp*2], *a1 = acc[ntp*2+1];
                    mma_bf16(a0, ahf, bh[0], bh[1]);
                    mma_bf16(a0, ahf, bl[0], bl[1]);
                    mma_bf16(a0, alf, bh[0], bh[1]);
                    mma_bf16(a1, ahf, bh[2], bh[3]);
                    mma_bf16(a1, ahf, bl[2], bl[3]);
                    mma_bf16(a1, alf, bh[2], bh[3]);
                }
            }
            #pragma unroll
            for (int half=0; half<2; half++){
                int row = row0 + m0 + gq + half*8;
                #pragma unroll
                for (int nt=0;nt<8;nt++){
                    int col = col0 + ncol0 + nt*8 + q*2;
                    *(float2*)&g_res[row*HD+col] =
                        make_float2(acc[nt][half*2], acc[nt][half*2+1]);
                }
            }
        }
    }
}

// ---------------- merged edge pass + CSR fill --------------------------------
__global__ __launch_bounds__(256) void k_edgefill(const float* __restrict__ e,
        const int* __restrict__ src, const int* __restrict__ dst,
        const float* __restrict__ W_fe, const float* __restrict__ attn_e){
    __shared__ float ce[NH];
    int wid = threadIdx.x>>5, lane = threadIdx.x&31;
    if (wid < NH){
        float p = 0.f;
        #pragma unroll
        for (int q=0;q<4;q++){
            int d = lane + q*32;
            p += W_fe[wid*HDIM+d]*attn_e[wid*HDIM+d];
        }
        #pragma unroll
        for (int off=16; off; off>>=1) p += __shfl_xor_sync(0xffffffffu, p, off);
        if (lane==0) ce[wid]=p;
    }
    __syncthreads();
    int ei = blockIdx.x*256 + threadIdx.x;
    if (ei >= N_EDGES) return;
    int s = src[ei], d = dst[ei];
    float ev = e[ei];
    float4 els = ((const float4*)g_el)[s];
    float4 erd = ((const float4*)g_er)[d];
    float sc[4];
    sc[0] = els.x + erd.x + ev*ce[0];
    sc[1] = els.y + erd.y + ev*ce[1];
    sc[2] = els.z + erd.z + ev*ce[2];
    sc[3] = els.w + erd.w + ev*ce[3];
    int pos = g_rowptr[d] + atomicAdd(&g_cursor[d], 1);
    g_esrc[pos] = s;
    #pragma unroll
    for (int hh=0;hh<4;hh++){
        float v = sc[hh];
        v = v > 0.f ? v : SLOPE_*v;
        float wv = expf(v);
        atomicAdd(&g_z[d*NH+hh], wv);
        g_wsH[hh*N_EDGES+pos] = wv;
    }
}

// ---------------- CSR scan ----------------------------------------------------
__global__ __launch_bounds__(1024) void k_scan(){
    __shared__ int sm[1024];
    int t = threadIdx.x;
    int base = t*32;
    int s = 0;
    #pragma unroll
    for (int i=0;i<32;i++) s += g_deg[base+i];
    sm[t]=s; __syncthreads();
    for (int off=1; off<1024; off<<=1){
        int v = (t>=off)? sm[t-off] : 0;
        __syncthreads();
        if (t>=off) sm[t]+=v;
        __syncthreads();
    }
    int run = sm[t]-s;
    for (int i=0;i<32;i++){ g_rowptr[base+i]=run; run += g_deg[base+i]; }
    if (t==1023) g_rowptr[N_NODES]=run;
}

// ---------------- aggregation (4x unrolled gathers) ---------------------------
__global__ __launch_bounds__(256) void k_agg(const float* __restrict__ gat_bias){
    int wid = threadIdx.x>>5, lane = threadIdx.x&31;
    int gw = blockIdx.x*8 + wid;
    int n = gw>>2, hh = gw&3;
    int beg = g_rowptr[n], end = g_rowptr[n+1];
    float zz = g_z[n*NH+hh];
    float zi = zz > 0.f ? 1.f/zz : 1.f;
    float4 acc = make_float4(0,0,0,0);
    const float4* ft4 = (const float4*)g_ft;
    const float* wp = g_wsH + hh*N_EDGES;
    int i = beg;
    for (; i+4<=end; i+=4){
        float w0 = wp[i],     w1 = wp[i+1],   w2 = wp[i+2],   w3 = wp[i+3];
        int   s0 = g_esrc[i], s1 = g_esrc[i+1], s2 = g_esrc[i+2], s3 = g_esrc[i+3];
        float4 v0 = ft4[s0*128 + hh*32 + lane];
        float4 v1 = ft4[s1*128 + hh*32 + lane];
        float4 v2 = ft4[s2*128 + hh*32 + lane];
        float4 v3 = ft4[s3*128 + hh*32 + lane];
        acc.x += w0*v0.x + w1*v1.x + w2*v2.x + w3*v3.x;
        acc.y += w0*v0.y + w1*v1.y + w2*v2.y + w3*v3.y;
        acc.z += w0*v0.z + w1*v1.z + w2*v2.z + w3*v3.z;
        acc.w += w0*v0.w + w1*v1.w + w2*v2.w + w3*v3.w;
    }
    for (; i<end; i++){
        float w0 = wp[i];
        int s0 = g_esrc[i];
        float4 v0 = ft4[s0*128 + hh*32 + lane];
        acc.x = fmaf(w0, v0.x, acc.x);
        acc.y = fmaf(w0, v0.y, acc.y);
        acc.z = fmaf(w0, v0.z, acc.z);
        acc.w = fmaf(w0, v0.w, acc.w);
    }
    int base = n*HD + hh*HDIM + lane*4;
    float4 r  = *(const float4*)&g_res[base];
    float4 bv = *(const float4*)&gat_bias[hh*HDIM + lane*4];
    float4 o;
    o.x = fmaxf(acc.x*zi + r.x + bv.x, 0.f);
    o.y = fmaxf(acc.y*zi + r.y + bv.y, 0.f);
    o.z = fmaxf(acc.z*zi + r.z + bv.z, 0.f);
    o.w = fmaxf(acc.w*zi + r.w + bv.w, 0.f);
    *(float4*)&g_res[base] = o;
}

// ---------------- MHA via mma, 512 threads + relu + residual + LN1 ----------
__global__ __launch_bounds__(512,1) void k_mha_mma(const float* __restrict__ bm,
        const float* __restrict__ h0, const float* __restrict__ g1,
        const float* __restrict__ be1){
    extern __shared__ char smem[];
    __shared__ float s_s1[128][2], s_s2[128][2];
    __nv_bfloat16* ah_s = (__nv_bfloat16*)(smem+GA_AH);
    __nv_bfloat16* al_s = (__nv_bfloat16*)(smem+GA_AL);
    const uint32_t sb = smem_u32(smem);
    const int tid = threadIdx.x, lane = tid&31, w = tid>>5;
    const int strip = w>>1, nh = w&1;
    const int m0 = strip*16, ncol0 = nh*64;
    const int row0 = blockIdx.x*128;

    const int a_r = lane & 15, a_c = (lane & 16) >> 1;
    const int b4_r = (lane & 7) + ((lane & 16) >> 1);
    const int b4_c = lane & 8;
    const int q = lane & 3, gq = lane >> 2;

    float acc[8][4];
    #pragma unroll
    for (int i=0;i<8;i++){ acc[i][0]=0.f; acc[i][1]=0.f; acc[i][2]=0.f; acc[i][3]=0.f; }

    for (int c=0; c<4; c++){
        __syncthreads();
        for (int i=tid;i<4096;i+=512){
            int m = i>>5, k4 = (i&31)*4;
            float4 v = *(const float4*)&g_res[(row0+m)*HD + c*128 + k4];
            __nv_bfloat162 hh, ll;
            bsplit(v.x, hh.x, ll.x); bsplit(v.y, hh.y, ll.y);
            *(__nv_bfloat162*)&ah_s[m*136+k4]   = hh;
            *(__nv_bfloat162*)&al_s[m*136+k4]   = ll;
            bsplit(v.z, hh.x, ll.x); bsplit(v.w, hh.y, ll.y);
            *(__nv_bfloat162*)&ah_s[m*136+k4+2] = hh;
            *(__nv_bfloat162*)&al_s[m*136+k4+2] = ll;
        }
        {
            const uint4* sh = (const uint4*)(g_wmth + c*128*136);
            const uint4* sl = (const uint4*)(g_wmtl + c*128*136);
            uint4* th = (uint4*)(smem+GA_BFH);
            uint4* tl = (uint4*)(smem+GA_BFL);
            for (int i=tid;i<2176;i+=512){ th[i]=sh[i]; tl[i]=sl[i]; }
        }
        __syncthreads();
        #pragma unroll
        for (int kk=0;kk<8;kk++){
            const int k0 = kk*16;
            uint32_t aaddr = sb + GA_AH + ((m0+a_r)*136 + k0 + a_c)*2;
            unsigned ahf[4], alf[4];
            ldsm4(ahf, aaddr);
            ldsm4(alf, aaddr + (GA_AL-GA_AH));
            #pragma unroll
            for (int ntp=0;ntp<4;ntp++){
                uint32_t baddr = sb + GA_BFH + ((ncol0+ntp*16+b4_r)*136 + k0 + b4_c)*2;
                unsigned bh[4], bl[4];
                ldsm4(bh, baddr);
                ldsm4(bl, baddr + (GA_BFL-GA_BFH));
                float* a0 = acc[ntp*2], *a1 = acc[ntp*2+1];
                mma_bf16(a0, ahf, bh[0], bh[1]);
                mma_bf16(a0, ahf, bl[0], bl[1]);
                mma_bf16(a0, alf, bh[0], bh[1]);
                mma_bf16(a1, ahf, bh[2], bh[3]);
                mma_bf16(a1, ahf, bl[2], bl[3]);
                mma_bf16(a1, alf, bh[2], bh[3]);
            }
        }
    }

    // epilogue: +bm, relu, +h0, LN1 (cross-warp-pair via smem) -> g_x1
    #pragma unroll
    for (int half=0; half<2; half++){
        int rl = m0 + gq + half*8;
        int row = row0 + rl;
        float tv[16], s1=0.f, s2=0.f;
        #pragma unroll
        for (int nt=0;nt<8;nt++){
            int col = ncol0 + nt*8 + q*2;
            float t0 = fmaxf(acc[nt][half*2+0] + bm[col],   0.f) + h0[row*HID_+col];
            float t1 = fmaxf(acc[nt][half*2+1] + bm[col+1], 0.f) + h0[row*HID_+col+1];
            tv[nt*2]=t0; tv[nt*2+1]=t1;
            s1 += t0+t1; s2 += t0*t0+t1*t1;
        }
        s1 += __shfl_xor_sync(0xffffffffu, s1, 1); s2 += __shfl_xor_sync(0xffffffffu, s2, 1);
        s1 += __shfl_xor_sync(0xffffffffu, s1, 2); s2 += __shfl_xor_sync(0xffffffffu, s2, 2);
        if (q==0){ s_s1[rl][nh]=s1; s_s2[rl][nh]=s2; }
        __syncthreads();
        float fs1 = s_s1[rl][0]+s_s1[rl][1];
        float fs2 = s_s2[rl][0]+s_s2[rl][1];
        float mean = fs1*(1.f/HID_);
        float var  = fs2*(1.f/HID_) - mean*mean;
        float rs   = rsqrtf(var + EPS_);
        #pragma unroll
        for (int nt=0;nt<8;nt++){
            int col = ncol0 + nt*8 + q*2;
            g_x1[row*HID_+col]   = (tv[nt*2]  -mean)*rs*g1[col]   + be1[col];
            g_x1[row*HID_+col+1] = (tv[nt*2+1]-mean)*rs*g1[col+1] + be1[col+1];
        }
        __syncthreads();
    }
}

// ---------------- FFN via mma, 512 threads + residual + LN2 ------------------
#define SM_XS_H 0
#define SM_XS_L 34816
#define SM_W1H  69632
#define SM_W1L  87040
#define SM_W2H  104448
#define SM_W2L  122880
#define SM_MIDH 141312
#define SM_MIDL 159744
#define SMEM_FFN 178176

__global__ __launch_bounds__(512,1) void k_ffn_mma(const float* __restrict__ b1v,
        const float* __restrict__ b2v, const float* __restrict__ g2,
        const float* __restrict__ be2, float* __restrict__ out){
    extern __shared__ char smem[];
    __shared__ float s_s1[128][2], s_s2[128][2];
    __nv_bfloat16* xs_h = (__nv_bfloat16*)(smem+SM_XS_H);
    __nv_bfloat16* xs_l = (__nv_bfloat16*)(smem+SM_XS_L);
    __nv_bfloat16* mid_h= (__nv_bfloat16*)(smem+SM_MIDH);
    __nv_bfloat16* mid_l= (__nv_bfloat16*)(smem+SM_MIDL);
    const uint32_t sb = smem_u32(smem);
    const int tid = threadIdx.x, lane = tid&31, w = tid>>5;
    const int strip = w>>1, nh = w&1;
    const int m0 = strip*16;
    const int row0 = blockIdx.x*128;

    for (int i=tid;i<128*128;i+=512){
        int m=i>>7, k=i&127;
        float v = g_x1[(row0+m)*HID_ + k];
        __nv_bfloat16 hv, lv; bsplit(v, hv, lv);
        xs_h[m*136+k] = hv;
        xs_l[m*136+k] = lv;
    }

    float acc2[8][4];
    #pragma unroll
    for (int i=0;i<8;i++){ acc2[i][0]=0.f; acc2[i][1]=0.f; acc2[i][2]=0.f; acc2[i][3]=0.f; }

    const int a_r = lane & 15, a_c = (lane & 16) >> 1;
    const int b4_r = (lane & 7) + ((lane & 16) >> 1);
    const int b4_c = lane & 8;
    const int q = lane & 3, gq = lane >> 2;

    for (int c=0; c<32; c++){
        __syncthreads();
        {
            const uint4* s1h = (const uint4*)(g_w1th + c*64*136);
            const uint4* s1l = (const uint4*)(g_w1tl + c*64*136);
            const uint4* s2h = (const uint4*)(g_w2th + c*128*72);
            const uint4* s2l = (const uint4*)(g_w2tl + c*128*72);
            uint4* t1h = (uint4*)(smem+SM_W1H); uint4* t1l = (uint4*)(smem+SM_W1L);
            uint4* t2h = (uint4*)(smem+SM_W2H); uint4* t2l = (uint4*)(smem+SM_W2L);
            for (int i=tid;i<1088;i+=512){ t1h[i]=s1h[i]; t1l[i]=s1l[i]; }
            for (int i=tid;i<1152;i+=512){ t2h[i]=s2h[i]; t2l[i]=s2l[i]; }
        }
        __syncthreads();

        // GEMM1: mid[128x64]; warp covers rows m0..+15, mid cols nh*32..+31
        float acc1[4][4];
        #pragma unroll
        for (int i=0;i<4;i++){ acc1[i][0]=0.f; acc1[i][1]=0.f; acc1[i][2]=0.f; acc1[i][3]=0.f; }
        #pragma unroll
        for (int kk=0;kk<8;kk++){
            const int k0 = kk*16;
            uint32_t aaddr = sb + SM_XS_H + ((m0+a_r)*136 + k0 + a_c)*2;
            unsigned ah[4], al[4];
            ldsm4(ah, aaddr);
            ldsm4(al, aaddr + (SM_XS_L - SM_XS_H));
            #pragma unroll
            for (int ntp=0;ntp<2;ntp++){
                uint32_t baddr = sb + SM_W1H + ((nh*32+ntp*16+b4_r)*136 + k0 + b4_c)*2;
                unsigned bh[4], bl[4];
                ldsm4(bh, baddr);
                ldsm4(bl, baddr + (SM_W1L - SM_W1H));
                float* a0 = acc1[ntp*2], *a1 = acc1[ntp*2+1];
                mma_bf16(a0, ah, bh[0], bh[1]);
                mma_bf16(a0, ah, bl[0], bl[1]);
                mma_bf16(a0, al, bh[0], bh[1]);
                mma_bf16(a1, ah, bh[2], bh[3]);
                mma_bf16(a1, ah, bl[2], bl[3]);
                mma_bf16(a1, al, bh[2], bh[3]);
            }
        }
        {
            const int r1 = m0 + gq, r2 = r1 + 8;
            #pragma unroll
            for (int nt=0;nt<4;nt++){
                int col = nh*32 + nt*8 + q*2;
                float bb0 = b1v[c*64+col], bb1 = b1v[c*64+col+1];
                float v0 = fmaxf(acc1[nt][0]+bb0, 0.f);
                float v1 = fmaxf(acc1[nt][1]+bb1, 0.f);
                float v2 = fmaxf(acc1[nt][2]+bb0, 0.f);
                float v3 = fmaxf(acc1[nt][3]+bb1, 0.f);
                __nv_bfloat162 hh, ll;
                bsplit(v0, hh.x, ll.x); bsplit(v1, hh.y, ll.y);
                *(__nv_bfloat162*)&mid_h[r1*72+col]=hh;
                *(__nv_bfloat162*)&mid_l[r1*72+col]=ll;
                bsplit(v2, hh.x, ll.x); bsplit(v3, hh.y, ll.y);
                *(__nv_bfloat162*)&mid_h[r2*72+col]=hh;
                *(__nv_bfloat162*)&mid_l[r2*72+col]=ll;
            }
        }
        __syncthreads();

        // GEMM2: acc2 += mid[rows m0..][64] @ W2^T ; warp covers out cols nh*64..+63
        #pragma unroll
        for (int kk=0;kk<4;kk++){
            const int k0 = kk*16;
            uint32_t aaddr = sb + SM_MIDH + ((m0+a_r)*72 + k0 + a_c)*2;
            unsigned ah[4], al[4];
            ldsm4(ah, aaddr);
            ldsm4(al, aaddr + (SM_MIDL - SM_MIDH));
            #pragma unroll
            for (int ntp=0;ntp<4;ntp++){
                uint32_t baddr = sb + SM_W2H + ((nh*64+ntp*16+b4_r)*72 + k0 + b4_c)*2;
                unsigned bh[4], bl[4];
                ldsm4(bh, baddr);
                ldsm4(bl, baddr + (SM_W2L - SM_W2H));
                float* a0 = acc2[ntp*2], *a1 = acc2[ntp*2+1];
                mma_bf16(a0, ah, bh[0], bh[1]);
                mma_bf16(a0, ah, bl[0], bl[1]);
                mma_bf16(a0, al, bh[0], bh[1]);
                mma_bf16(a1, ah, bh[2], bh[3]);
                mma_bf16(a1, ah, bl[2], bl[3]);
                mma_bf16(a1, al, bh[2], bh[3]);
            }
        }
    }

    // epilogue: +b2 + residual + LN2 (cross-warp-pair via smem)
    #pragma unroll
    for (int half=0; half<2; half++){
        int rl = m0 + gq + half*8;
        int grow = row0 + rl;
        float tv[16], s1=0.f, s2=0.f;
        #pragma unroll
        for (int nt=0;nt<8;nt++){
            int col = nh*64 + nt*8 + q*2;
            float t0 = acc2[nt][half*2+0] + b2v[col]   + g_x1[grow*HID_+col];
            float t1 = acc2[nt][half*2+1] + b2v[col+1] + g_x1[grow*HID_+col+1];
            tv[nt*2]=t0; tv[nt*2+1]=t1;
            s1 += t0+t1; s2 += t0*t0+t1*t1;
        }
        s1 += __shfl_xor_sync(0xffffffffu, s1, 1); s2 += __shfl_xor_sync(0xffffffffu, s2, 1);
        s1 += __shfl_xor_sync(0xffffffffu, s1, 2); s2 += __shfl_xor_sync(0xffffffffu, s2, 2);
        if (q==0){ s_s1[rl][nh]=s1; s_s2[rl][nh]=s2; }
        __syncthreads();
        float fs1 = s_s1[rl][0]+s_s1[rl][1];
        float fs2 = s_s2[rl][0]+s_s2[rl][1];
        float mean = fs1*(1.f/HID_);
        float var  = fs2*(1.f/HID_) - mean*mean;
        float rs   = rsqrtf(var + EPS_);
        #pragma unroll
        for (int nt=0;nt<8;nt++){
            int col = nh*64 + nt*8 + q*2;
            out[grow*HID_+col]   = (tv[nt*2]  -mean)*rs*g2[col]   + be2[col];
            out[grow*HID_+col+1] = (tv[nt*2+1]-mean)*rs*g2[col+1] + be2[col+1];
        }
        __syncthreads();
    }
}

// ---------------- launch ----------------------------------------------------
extern "C" void kernel_launch(void* const* d_in, const int* in_sizes, int n_in,
                              void* d_out, int out_size){
    int o = (in_sizes[4] == 1) ? 1 : 0;
    const float* h       = (const float*)d_in[0];
    const float* e       = (const float*)d_in[1];
    const int*   src     = (const int*)  d_in[2];
    const int*   dst     = (const int*)  d_in[3];
    const float* W_fc    = (const float*)d_in[4+o];
    const float* attn_l  = (const float*)d_in[5+o];
    const float* attn_r  = (const float*)d_in[6+o];
    const float* W_fe    = (const float*)d_in[7+o];
    const float* attn_e  = (const float*)d_in[8+o];
    const float* W_res   = (const float*)d_in[9+o];
    const float* gatb    = (const float*)d_in[10+o];
    const float* W_mha   = (const float*)d_in[11+o];
    const float* b_mha   = (const float*)d_in[12+o];
    const float* n1_g    = (const float*)d_in[13+o];
    const float* n1_b    = (const float*)d_in[14+o];
    const float* n2_g    = (const float*)d_in[15+o];
    const float* n2_b    = (const float*)d_in[16+o];
    const float* W1      = (const float*)d_in[17+o];
    const float* b1      = (const float*)d_in[18+o];
    const float* W2      = (const float*)d_in[19+o];
    const float* b2      = (const float*)d_in[20+o];
    float* out = (float*)d_out;

    cudaFuncSetAttribute(k_ffn_mma,  cudaFuncAttributeMaxDynamicSharedMemorySize, SMEM_FFN);
    cudaFuncSetAttribute(k_gemmA_mma,cudaFuncAttributeMaxDynamicSharedMemorySize, SMEM_GA);
    cudaFuncSetAttribute(k_mha_mma,  cudaFuncAttributeMaxDynamicSharedMemorySize, SMEM_MH);

    k_init<<<512,256>>>();
    k_prep<<<1024,256>>>(W1, W2, W_fc, W_res, W_mha);
    k_deg<<<N_EDGES/256,256>>>(dst);
    dim3 gA(64, 4);
    k_gemmA_mma<<<gA,512,SMEM_GA>>>(h, attn_l, attn_r);
    k_scan<<<1,1024>>>();
    k_edgefill<<<N_EDGES/256,256>>>(e, src, dst, W_fe, attn_e);
    k_agg<<<N_NODES*NH/8,256>>>(gatb);
    k_mha_mma<<<N_NODES/128,512,SMEM_MH>>>(b_mha, h, n1_g, n1_b);
    k_ffn_mma<<<N_NODES/128,512,SMEM_FFN>>>(b1, b2, n2_g, n2_b, out);
}